// round 9
// baseline (speedup 1.0000x reference)
#include <cuda_runtime.h>
#include <cuda_fp16.h>

#define NN 100000
#define EE 1600000
#define GG 1024

typedef unsigned long long ull;

// -------------------- device scratch --------------------
__device__ float g_A[(size_t)NN * 64];     // layer-1 aggregation output (fp32)
__device__ __half g_A2[(size_t)NN * 64];   // layer-2 aggregation output (fp16)
__device__ float g_B[(size_t)NN * 64];     // raw layer outputs (fp32)
__device__ uint4 g_H[(size_t)NN * 8];      // activated features fp16 (64 halves/node)
__device__ float g_xpad[(size_t)NN * 16];
__device__ int   g_off[NN + 1];
__device__ int   g_cur[NN];
__device__ int   g_bsum[128];
__device__ int2  g_epack[EE];              // (src, weight-bits) grouped by dst
__device__ int   g_goff[GG + 1];
__device__ float g_stats[256];             // [0:128) layer0, [128:256) layer1

__device__ __forceinline__ void fma2(ull& d, ull a, ull b) {
    asm("fma.rn.f32x2 %0, %1, %2, %0;" : "+l"(d) : "l"(a), "l"(b));
}
__device__ __forceinline__ float2 unpack2(ull v) {
    float2 r; asm("mov.b64 {%0,%1}, %2;" : "=f"(r.x), "=f"(r.y) : "l"(v)); return r;
}
__device__ __forceinline__ ull pack2(float lo, float hi) {
    ull r; asm("mov.b64 %0, {%1,%2};" : "=l"(r) : "f"(lo), "f"(hi)); return r;
}

// -------------------- fused prep: hist(x4) + xpad(x4) + graph bounds ------------
// thread i: 4 hist edges, one float4 of xpad, one goff node.
__global__ void prep(const float* __restrict__ x, float* __restrict__ xp,
                     const int* __restrict__ dst, int* __restrict__ off,
                     const int* __restrict__ batch, int* __restrict__ goff) {
    int i = blockIdx.x * blockDim.x + threadIdx.x;
    int e = i * 4;
    if (e + 3 < EE) {
        int d0 = dst[e], d1 = dst[e + 1], d2 = dst[e + 2], d3 = dst[e + 3];
        atomicAdd(&off[d0 + 1], 1);
        atomicAdd(&off[d1 + 1], 1);
        atomicAdd(&off[d2 + 1], 1);
        atomicAdd(&off[d3 + 1], 1);
    } else {
        for (int j = 0; j < 4 && e + j < EE; j++) atomicAdd(&off[dst[e + j] + 1], 1);
    }
    if (i < NN * 4) {   // one float4 of xpad: columns c0..c0+3 of node n
        int n = i >> 2, c0 = (i & 3) * 4;
        float4 v;
        v.x = (c0 + 0 < 9) ? x[n * 9 + c0 + 0] : 0.f;
        v.y = (c0 + 1 < 9) ? x[n * 9 + c0 + 1] : 0.f;
        v.z = (c0 + 2 < 9) ? x[n * 9 + c0 + 2] : 0.f;
        v.w = (c0 + 3 < 9) ? x[n * 9 + c0 + 3] : 0.f;
        ((float4*)xp)[i] = v;
    }
    if (i < NN) {
        int bi = batch[i];
        if (i == 0) { for (int g = 0; g <= bi; g++) goff[g] = 0; }
        else { int bp = batch[i - 1]; for (int g = bp + 1; g <= bi; g++) goff[g] = i; }
        if (i == NN - 1) { for (int g = bi + 1; g <= GG; g++) goff[g] = NN; }
    }
}

// -------------------- scan --------------------
__global__ void scan1(int* __restrict__ off, int* __restrict__ bsum) {
    __shared__ int ws[32];
    int g = blockIdx.x * 1024 + threadIdx.x;
    int v = (g <= NN) ? off[g] : 0;
    int lane = threadIdx.x & 31;
#pragma unroll
    for (int d = 1; d < 32; d <<= 1) { int t = __shfl_up_sync(~0u, v, d); if (lane >= d) v += t; }
    if (lane == 31) ws[threadIdx.x >> 5] = v;
    __syncthreads();
    if (threadIdx.x < 32) {
        int t = ws[threadIdx.x];
#pragma unroll
        for (int d = 1; d < 32; d <<= 1) { int u = __shfl_up_sync(~0u, t, d); if (threadIdx.x >= d) t += u; }
        ws[threadIdx.x] = t;
    }
    __syncthreads();
    if (threadIdx.x >= 32) v += ws[(threadIdx.x >> 5) - 1];
    if (g <= NN) off[g] = v;
    if (threadIdx.x == 1023) bsum[blockIdx.x] = v;
}

__global__ void scan3f(int* __restrict__ off, const int* __restrict__ bsum, int* __restrict__ cur) {
    __shared__ int red[32];
    __shared__ int sadd;
    int t = threadIdx.x;
    int v = (t < blockIdx.x) ? bsum[t] : 0;
#pragma unroll
    for (int d = 16; d; d >>= 1) v += __shfl_down_sync(~0u, v, d);
    if ((t & 31) == 0) red[t >> 5] = v;
    __syncthreads();
    if (t == 0) { int r = 0; for (int w = 0; w < 32; w++) r += red[w]; sadd = r; }
    __syncthreads();
    int g = blockIdx.x * 1024 + t;
    if (g > NN) return;
    int val = off[g] + sadd;
    off[g] = val;
    if (g < NN) cur[g] = val;
}

// -------------------- placement: 4 edges/thread (independent atomic chains) ----
__global__ void place_kernel(const int* __restrict__ src, const int* __restrict__ dst,
                             const float* __restrict__ ew, int* __restrict__ cur,
                             int2* __restrict__ epack) {
    int i = blockIdx.x * blockDim.x + threadIdx.x;
    int e = i * 4;
    if (e + 3 < EE) {
        int d0 = dst[e], d1 = dst[e + 1], d2 = dst[e + 2], d3 = dst[e + 3];
        int s0 = src[e], s1 = src[e + 1], s2 = src[e + 2], s3 = src[e + 3];
        float w0 = ew[e], w1 = ew[e + 1], w2 = ew[e + 2], w3 = ew[e + 3];
        int p0 = atomicAdd(&cur[d0], 1);
        int p1 = atomicAdd(&cur[d1], 1);
        int p2 = atomicAdd(&cur[d2], 1);
        int p3 = atomicAdd(&cur[d3], 1);
        epack[p0] = make_int2(s0, __float_as_int(w0));
        epack[p1] = make_int2(s1, __float_as_int(w1));
        epack[p2] = make_int2(s2, __float_as_int(w2));
        epack[p3] = make_int2(s3, __float_as_int(w3));
    } else {
        for (int j = 0; j < 4 && e + j < EE; j++) {
            int p = atomicAdd(&cur[dst[e + j]], 1);
            epack[p] = make_int2(src[e + j], __float_as_int(ew[e + j]));
        }
    }
}

// -------------------- layer-0 CSR aggregation (fp32, unroll-8) ------------------
__global__ void __launch_bounds__(256) agg_csr4(
    const float* __restrict__ h, const int* __restrict__ rowptr,
    const int2* __restrict__ epack, float* __restrict__ agg, float* __restrict__ stats) {
    if (blockIdx.x == 0) stats[threadIdx.x] = 0.f;   // zero both stats banks
    int node = blockIdx.x * 64 + (threadIdx.x >> 2);
    int lane = threadIdx.x & 3;
    if (node >= NN) return;
    int beg = rowptr[node], end = rowptr[node + 1];
    float4 acc = make_float4(0.f, 0.f, 0.f, 0.f);
    int i = beg;
    for (; i + 7 < end; i += 8) {
        int2 ee[8];
        float4 vv[8];
#pragma unroll
        for (int j = 0; j < 8; j++) ee[j] = epack[i + j];
#pragma unroll
        for (int j = 0; j < 8; j++) vv[j] = ((const float4*)h)[(size_t)ee[j].x * 4 + lane];
#pragma unroll
        for (int j = 0; j < 8; j++) {
            float w = __int_as_float(ee[j].y);
            acc.x = fmaf(vv[j].x, w, acc.x); acc.y = fmaf(vv[j].y, w, acc.y);
            acc.z = fmaf(vv[j].z, w, acc.z); acc.w = fmaf(vv[j].w, w, acc.w);
        }
    }
    for (; i < end; ++i) {
        int2 ep = epack[i];
        float w = __int_as_float(ep.y);
        float4 v = ((const float4*)h)[(size_t)ep.x * 4 + lane];
        acc.x = fmaf(v.x, w, acc.x); acc.y = fmaf(v.y, w, acc.y);
        acc.z = fmaf(v.z, w, acc.z); acc.w = fmaf(v.w, w, acc.w);
    }
    ((float4*)agg)[(size_t)node * 4 + lane] = acc;
}

// -------------------- fp16 CSR aggregation (unroll-8, templated output) ---------
__device__ __forceinline__ void accum8(float* acc, uint4 r, float w) {
    __half2* hp = (__half2*)&r;
#pragma unroll
    for (int j = 0; j < 4; j++) {
        float2 f = __half22float2(hp[j]);
        acc[2 * j]     = fmaf(f.x, w, acc[2 * j]);
        acc[2 * j + 1] = fmaf(f.y, w, acc[2 * j + 1]);
    }
}

template <bool HALF_OUT>
__global__ void __launch_bounds__(256) agg_csr_h(
    const uint4* __restrict__ h, const int* __restrict__ rowptr,
    const int2* __restrict__ epack, void* __restrict__ aggv) {
    int node = blockIdx.x * 32 + (threadIdx.x >> 3);
    int lane = threadIdx.x & 7;
    if (node >= NN) return;
    int beg = rowptr[node], end = rowptr[node + 1];
    float acc[8];
#pragma unroll
    for (int j = 0; j < 8; j++) acc[j] = 0.f;
    int i = beg;
    for (; i + 7 < end; i += 8) {
        int2 ee[8];
        uint4 rr[8];
#pragma unroll
        for (int j = 0; j < 8; j++) ee[j] = epack[i + j];
#pragma unroll
        for (int j = 0; j < 8; j++) rr[j] = h[(size_t)ee[j].x * 8 + lane];
#pragma unroll
        for (int j = 0; j < 8; j++) accum8(acc, rr[j], __int_as_float(ee[j].y));
    }
    for (; i < end; ++i) {
        int2 e0 = epack[i];
        uint4 r0 = h[(size_t)e0.x * 8 + lane];
        accum8(acc, r0, __int_as_float(e0.y));
    }
    if (HALF_OUT) {
        __half2 o0 = __floats2half2_rn(acc[0], acc[1]);
        __half2 o1 = __floats2half2_rn(acc[2], acc[3]);
        __half2 o2 = __floats2half2_rn(acc[4], acc[5]);
        __half2 o3 = __floats2half2_rn(acc[6], acc[7]);
        uint4 o;
        o.x = *(unsigned*)&o0; o.y = *(unsigned*)&o1;
        o.z = *(unsigned*)&o2; o.w = *(unsigned*)&o3;
        ((uint4*)aggv)[(size_t)node * 8 + lane] = o;
    } else {
        float* dstp = &((float*)aggv)[(size_t)node * 64 + lane * 8];
        *(float4*)dstp       = make_float4(acc[0], acc[1], acc[2], acc[3]);
        *(float4*)(dstp + 4) = make_float4(acc[4], acc[5], acc[6], acc[7]);
    }
}

// -------------------- layer-0 node update (K=9, scalar) --------------------
__global__ void __launch_bounds__(128) node_update9(
    const float* __restrict__ Ag, const float* __restrict__ Xin,
    const float* __restrict__ Wrel, const float* __restrict__ Wroot,
    const float* __restrict__ bias, float* __restrict__ Out, float* stats) {
    constexpr int K = 9, PAD = 17, C4 = 4;
    extern __shared__ float sm[];
    float* sA   = sm;
    float* sX   = sA + 64 * PAD;
    float* sWr  = sX + 64 * PAD;
    float* sWo  = sWr + K * 64;
    float* sSum = sWo + K * 64;
    float* sSq  = sSum + 64;

    const int tid = threadIdx.x;
    const int base = blockIdx.x * 64;

    for (int i = tid; i < K * 16; i += 128) {
        ((float4*)sWr)[i] = ((const float4*)Wrel)[i];
        ((float4*)sWo)[i] = ((const float4*)Wroot)[i];
    }
    for (int i = tid; i < 64 * C4; i += 128) {
        int r = i / C4, c = i - r * C4;
        int n = base + r;
        float4 va = make_float4(0.f, 0.f, 0.f, 0.f), vx = va;
        if (n < NN) {
            va = *(const float4*)&Ag[(size_t)n * 16 + c * 4];
            vx = *(const float4*)&Xin[(size_t)n * 16 + c * 4];
        }
        int o = r * PAD + c * 4;
        sA[o] = va.x; sA[o + 1] = va.y; sA[o + 2] = va.z; sA[o + 3] = va.w;
        sX[o] = vx.x; sX[o + 1] = vx.y; sX[o + 2] = vx.z; sX[o + 3] = vx.w;
    }
    if (tid < 64) { sSum[tid] = 0.f; sSq[tid] = 0.f; }
    __syncthreads();

    const int fg = (tid & 7) * 8;
    const int ng = (tid >> 3) * 4;

    float acc[4][8];
#pragma unroll
    for (int i = 0; i < 4; i++)
#pragma unroll
        for (int j = 0; j < 8; j++) acc[i][j] = 0.f;

#pragma unroll
    for (int k = 0; k < K; ++k) {
        float a[4], xv[4];
#pragma unroll
        for (int i = 0; i < 4; i++) {
            a[i]  = sA[(ng + i) * PAD + k];
            xv[i] = sX[(ng + i) * PAD + k];
        }
        float wr[8], wo[8];
        *(float4*)&wr[0] = *(const float4*)&sWr[k * 64 + fg];
        *(float4*)&wr[4] = *(const float4*)&sWr[k * 64 + fg + 4];
        *(float4*)&wo[0] = *(const float4*)&sWo[k * 64 + fg];
        *(float4*)&wo[4] = *(const float4*)&sWo[k * 64 + fg + 4];
#pragma unroll
        for (int i = 0; i < 4; i++)
#pragma unroll
            for (int j = 0; j < 8; j++)
                acc[i][j] = fmaf(xv[i], wo[j], fmaf(a[i], wr[j], acc[i][j]));
    }

    float bz[8];
    *(float4*)&bz[0] = *(const float4*)&bias[fg];
    *(float4*)&bz[4] = *(const float4*)&bias[fg + 4];

    float s[8], q[8];
#pragma unroll
    for (int j = 0; j < 8; j++) { s[j] = 0.f; q[j] = 0.f; }

#pragma unroll
    for (int i = 0; i < 4; i++) {
        int n = base + ng + i;
        if (n < NN) {
            float o[8];
#pragma unroll
            for (int j = 0; j < 8; j++) o[j] = acc[i][j] + bz[j];
            *(float4*)&Out[(size_t)n * 64 + fg]     = make_float4(o[0], o[1], o[2], o[3]);
            *(float4*)&Out[(size_t)n * 64 + fg + 4] = make_float4(o[4], o[5], o[6], o[7]);
#pragma unroll
            for (int j = 0; j < 8; j++) { s[j] += o[j]; q[j] += o[j] * o[j]; }
        }
    }
#pragma unroll
    for (int j = 0; j < 8; j++) {
        atomicAdd(&sSum[fg + j], s[j]);
        atomicAdd(&sSq[fg + j], q[j]);
    }
    __syncthreads();
    if (tid < 64) {
        atomicAdd(&stats[tid], sSum[tid]);
        atomicAdd(&stats[64 + tid], sSq[tid]);
    }
}

// -------------------- f32x2 node update (K=64), fp16 Xin --------------------
__global__ void __launch_bounds__(128) node_update64(
    const float* __restrict__ Ag, const uint4* __restrict__ Xh,
    const float* __restrict__ Wrel, const float* __restrict__ Wroot,
    const float* __restrict__ bias, float* __restrict__ Out, float* stats) {
    constexpr int PAD = 66;
    extern __shared__ float sm[];
    float* sA   = sm;
    float* sX   = sA + 64 * PAD;
    ull*   sWr  = (ull*)(sX + 64 * PAD);
    ull*   sWo  = sWr + 32 * 64;
    float* sSum = (float*)(sWo + 32 * 64);
    float* sSq  = sSum + 64;

    const int tid = threadIdx.x;
    const int base = blockIdx.x * 64;

    for (int idx = tid; idx < 32 * 16; idx += 128) {
        int k2 = idx >> 4, c4 = idx & 15;
        float4 r0 = ((const float4*)Wrel)[(2 * k2) * 16 + c4];
        float4 r1 = ((const float4*)Wrel)[(2 * k2 + 1) * 16 + c4];
        ull* p = &sWr[k2 * 64 + c4 * 4];
        p[0] = pack2(r0.x, r1.x); p[1] = pack2(r0.y, r1.y);
        p[2] = pack2(r0.z, r1.z); p[3] = pack2(r0.w, r1.w);
        r0 = ((const float4*)Wroot)[(2 * k2) * 16 + c4];
        r1 = ((const float4*)Wroot)[(2 * k2 + 1) * 16 + c4];
        p = &sWo[k2 * 64 + c4 * 4];
        p[0] = pack2(r0.x, r1.x); p[1] = pack2(r0.y, r1.y);
        p[2] = pack2(r0.z, r1.z); p[3] = pack2(r0.w, r1.w);
    }
    for (int i = tid; i < 64 * 16; i += 128) {
        int r = i >> 4, c = i & 15;
        int n = base + r;
        float4 va = make_float4(0.f, 0.f, 0.f, 0.f);
        if (n < NN) va = *(const float4*)&Ag[(size_t)n * 64 + c * 4];
        int o = r * PAD + c * 4;
        sA[o] = va.x; sA[o + 1] = va.y; sA[o + 2] = va.z; sA[o + 3] = va.w;
    }
    for (int i = tid; i < 64 * 8; i += 128) {
        int r = i >> 3, c = i & 7;
        int n = base + r;
        uint4 v = make_uint4(0u, 0u, 0u, 0u);
        if (n < NN) v = Xh[(size_t)n * 8 + c];
        __half2* hp = (__half2*)&v;
        float* o = &sX[r * PAD + c * 8];
#pragma unroll
        for (int j = 0; j < 4; j++) {
            float2 f = __half22float2(hp[j]);
            o[2 * j] = f.x; o[2 * j + 1] = f.y;
        }
    }
    if (tid < 64) { sSum[tid] = 0.f; sSq[tid] = 0.f; }
    __syncthreads();

    const int f0 = (tid & 7) * 2;
    const int ng = (tid >> 3) * 4;

    ull acc2[4][8];
#pragma unroll
    for (int i = 0; i < 4; i++)
#pragma unroll
        for (int j = 0; j < 8; j++) acc2[i][j] = 0ull;

#pragma unroll 2
    for (int k2 = 0; k2 < 32; ++k2) {
        ull av[4], xv[4];
#pragma unroll
        for (int i = 0; i < 4; i++) {
            av[i] = *(const ull*)&sA[(ng + i) * PAD + 2 * k2];
            xv[i] = *(const ull*)&sX[(ng + i) * PAD + 2 * k2];
        }
#pragma unroll
        for (int c = 0; c < 4; c++) {
            ulonglong2 wr = *(const ulonglong2*)&sWr[k2 * 64 + f0 + 16 * c];
            ulonglong2 wo = *(const ulonglong2*)&sWo[k2 * 64 + f0 + 16 * c];
#pragma unroll
            for (int i = 0; i < 4; i++) {
                fma2(acc2[i][2 * c],     av[i], wr.x);
                fma2(acc2[i][2 * c + 1], av[i], wr.y);
                fma2(acc2[i][2 * c],     xv[i], wo.x);
                fma2(acc2[i][2 * c + 1], xv[i], wo.y);
            }
        }
    }

    float bz[8];
#pragma unroll
    for (int c = 0; c < 4; c++) {
        float2 b2 = *(const float2*)&bias[f0 + 16 * c];
        bz[2 * c] = b2.x; bz[2 * c + 1] = b2.y;
    }

    float s[8], q[8];
#pragma unroll
    for (int j = 0; j < 8; j++) { s[j] = 0.f; q[j] = 0.f; }

#pragma unroll
    for (int i = 0; i < 4; i++) {
        int n = base + ng + i;
        if (n < NN) {
#pragma unroll
            for (int c = 0; c < 4; c++) {
                float2 e0 = unpack2(acc2[i][2 * c]);
                float2 e1 = unpack2(acc2[i][2 * c + 1]);
                float o0 = e0.x + e0.y + bz[2 * c];
                float o1 = e1.x + e1.y + bz[2 * c + 1];
                *(float2*)&Out[(size_t)n * 64 + f0 + 16 * c] = make_float2(o0, o1);
                s[2 * c] += o0; q[2 * c] += o0 * o0;
                s[2 * c + 1] += o1; q[2 * c + 1] += o1 * o1;
            }
        }
    }
#pragma unroll
    for (int c = 0; c < 4; c++) {
        atomicAdd(&sSum[f0 + 16 * c],     s[2 * c]);
        atomicAdd(&sSum[f0 + 16 * c + 1], s[2 * c + 1]);
        atomicAdd(&sSq[f0 + 16 * c],      q[2 * c]);
        atomicAdd(&sSq[f0 + 16 * c + 1],  q[2 * c + 1]);
    }
    __syncthreads();
    if (tid < 64) {
        atomicAdd(&stats[tid], sSum[tid]);
        atomicAdd(&stats[64 + tid], sSq[tid]);
    }
}

// -------------------- BN finalize + apply + ReLU + fp16 convert (fused) --------
__global__ void __launch_bounds__(256) bn_act_h(
    const float* __restrict__ in, const float* __restrict__ stats,
    const float* __restrict__ g, const float* __restrict__ be,
    uint4* __restrict__ outh) {
    __shared__ float sc[64], sh[64];
    if (threadIdx.x < 64) {
        int f = threadIdx.x;
        const float inv = 1.f / (float)NN;
        float m = stats[f] * inv;
        float var = stats[64 + f] * inv - m * m;
        float s = g[f] * rsqrtf(var + 1e-5f);
        sc[f] = s;
        sh[f] = fmaf(-m, s, be[f]);
    }
    __syncthreads();
    int i = blockIdx.x * blockDim.x + threadIdx.x;
    if (i >= NN * 8) return;
    int c8 = (i & 7) * 8;
    float4 a = ((const float4*)in)[2 * i];
    float4 b = ((const float4*)in)[2 * i + 1];
    a.x = fmaxf(fmaf(a.x, sc[c8 + 0], sh[c8 + 0]), 0.f);
    a.y = fmaxf(fmaf(a.y, sc[c8 + 1], sh[c8 + 1]), 0.f);
    a.z = fmaxf(fmaf(a.z, sc[c8 + 2], sh[c8 + 2]), 0.f);
    a.w = fmaxf(fmaf(a.w, sc[c8 + 3], sh[c8 + 3]), 0.f);
    b.x = fmaxf(fmaf(b.x, sc[c8 + 4], sh[c8 + 4]), 0.f);
    b.y = fmaxf(fmaf(b.y, sc[c8 + 5], sh[c8 + 5]), 0.f);
    b.z = fmaxf(fmaf(b.z, sc[c8 + 6], sh[c8 + 6]), 0.f);
    b.w = fmaxf(fmaf(b.w, sc[c8 + 7], sh[c8 + 7]), 0.f);
    __half2 h0 = __floats2half2_rn(a.x, a.y);
    __half2 h1 = __floats2half2_rn(a.z, a.w);
    __half2 h2 = __floats2half2_rn(b.x, b.y);
    __half2 h3 = __floats2half2_rn(b.z, b.w);
    uint4 o;
    o.x = *(unsigned*)&h0; o.y = *(unsigned*)&h1;
    o.z = *(unsigned*)&h2; o.w = *(unsigned*)&h3;
    outh[i] = o;
}

// -------------------- layer-2 pooled GEMM + MLP head (fp16 agg) --------------
__global__ void pool2_head(const __half* __restrict__ Ag, const uint4* __restrict__ Xh,
                           const float* __restrict__ W2rel, const float* __restrict__ W2root,
                           const float* __restrict__ b2, const int* __restrict__ goff,
                           const float* __restrict__ Wl1, const float* __restrict__ bl1,
                           const float* __restrict__ Wl2, const float* __restrict__ bl2,
                           float* __restrict__ out) {
    __shared__ float sAg[64], sXp[64], sPool[64], sz[64];
    int g = blockIdx.x, t = threadIdx.x;
    int beg = goff[g], end = goff[g + 1];
    const __half* xh = (const __half*)Xh;
    float sa = 0.f, sx = 0.f;
    for (int n = beg; n < end; ++n) {
        sa += __half2float(Ag[(size_t)n * 64 + t]);
        sx += __half2float(xh[(size_t)n * 64 + t]);
    }
    sAg[t] = sa; sXp[t] = sx;
    __syncthreads();
    float cnt = (float)(end - beg);
    float acc = cnt * b2[t];
#pragma unroll 8
    for (int k = 0; k < 64; k++)
        acc += sAg[k] * W2rel[k * 64 + t] + sXp[k] * W2root[k * 64 + t];
    sPool[t] = acc / fmaxf(cnt, 1.f);
    __syncthreads();
    float z = bl1[t];
#pragma unroll 8
    for (int k = 0; k < 64; k++) z = fmaf(sPool[k], Wl1[k * 64 + t], z);
    sz[t] = fmaxf(z, 0.f);
    __syncthreads();
    if (t < 6) {
        float o = bl2[t];
#pragma unroll 8
        for (int k = 0; k < 64; k++) o = fmaf(sz[k], Wl2[k * 6 + t], o);
        out[g * 6 + t] = o;
    }
}

// -------------------- launch --------------------
extern "C" void kernel_launch(void* const* d_in, const int* in_sizes, int n_in,
                              void* d_out, int out_size) {
    const float* x     = (const float*)d_in[0];
    const int*   ei    = (const int*)d_in[1];
    const float* ew    = (const float*)d_in[2];
    const int*   batch = (const int*)d_in[3];
    const float *Wrel0 = (const float*)d_in[4],  *Wroot0 = (const float*)d_in[5],  *b0 = (const float*)d_in[6];
    const float *Wrel1 = (const float*)d_in[7],  *Wroot1 = (const float*)d_in[8],  *b1 = (const float*)d_in[9];
    const float *Wrel2 = (const float*)d_in[10], *Wroot2 = (const float*)d_in[11], *b2 = (const float*)d_in[12];
    const float *g0 = (const float*)d_in[13], *be0 = (const float*)d_in[14];
    const float *g1 = (const float*)d_in[15], *be1 = (const float*)d_in[16];
    const float *Wl1 = (const float*)d_in[17], *bl1 = (const float*)d_in[18];
    const float *Wl2 = (const float*)d_in[19], *bl2 = (const float*)d_in[20];
    float* out = (float*)d_out;

    const int* src = ei;
    const int* dst = ei + EE;

    float *pA, *pB, *pX, *pStats;
    __half* pA2;
    uint4* pH;
    int *pOff, *pCur, *pBsum, *pGoff;
    int2* pEpack;
    cudaGetSymbolAddress((void**)&pA, g_A);
    cudaGetSymbolAddress((void**)&pA2, g_A2);
    cudaGetSymbolAddress((void**)&pB, g_B);
    cudaGetSymbolAddress((void**)&pH, g_H);
    cudaGetSymbolAddress((void**)&pX, g_xpad);
    cudaGetSymbolAddress((void**)&pStats, g_stats);
    cudaGetSymbolAddress((void**)&pOff, g_off);
    cudaGetSymbolAddress((void**)&pCur, g_cur);
    cudaGetSymbolAddress((void**)&pBsum, g_bsum);
    cudaGetSymbolAddress((void**)&pGoff, g_goff);
    cudaGetSymbolAddress((void**)&pEpack, g_epack);

    const int smem64 = 64 * 66 * 4 * 2 + 32 * 64 * 8 * 2 + 128 * 4;  // 67072 B
    const int smem9  = (64 * 17 * 2 + 9 * 64 * 2 + 128) * (int)sizeof(float);
    cudaFuncSetAttribute((const void*)node_update64,
                         cudaFuncAttributeMaxDynamicSharedMemorySize, smem64);

    const int NB = (NN + 63) / 64;
    const int SCAN_BLOCKS = (NN + 1 + 1023) / 1024;
    const int Q4 = (EE / 4 + 255) / 256;   // 4 edges/thread grids

    // ---- CSR build + prep ----
    cudaMemsetAsync(pOff, 0, (NN + 1) * sizeof(int));
    prep<<<Q4, 256>>>(x, pX, dst, pOff, batch, pGoff);
    scan1<<<SCAN_BLOCKS, 1024>>>(pOff, pBsum);
    scan3f<<<SCAN_BLOCKS, 1024>>>(pOff, pBsum, pCur);
    place_kernel<<<Q4, 256>>>(src, dst, ew, pCur, pEpack);

    // ---- layer 0 ----
    agg_csr4<<<(NN + 63) / 64, 256>>>(pX, pOff, pEpack, pA, pStats);
    node_update9<<<NB, 128, smem9>>>(pA, pX, Wrel0, Wroot0, b0, pB, pStats);
    bn_act_h<<<(NN * 8 + 255) / 256, 256>>>(pB, pStats, g0, be0, pH);

    // ---- layer 1 (split gather + GEMM, unroll-8 gather) ----
    agg_csr_h<false><<<(NN + 31) / 32, 256>>>(pH, pOff, pEpack, pA);
    node_update64<<<NB, 128, smem64>>>(pA, pH, Wrel1, Wroot1, b1, pB, pStats + 128);
    bn_act_h<<<(NN * 8 + 255) / 256, 256>>>(pB, pStats + 128, g1, be1, pH);

    // ---- layer 2: fp16 gather then pooled GEMM + head ----
    agg_csr_h<true><<<(NN + 31) / 32, 256>>>(pH, pOff, pEpack, pA2);
    pool2_head<<<GG, 64>>>(pA2, pH, Wrel2, Wroot2, b2, pGoff, Wl1, bl1, Wl2, bl2, out);
}

// round 10
// speedup vs baseline: 1.0340x; 1.0340x over previous
#include <cuda_runtime.h>
#include <cuda_fp16.h>

#define NN 100000
#define EE 1600000
#define GG 1024
#define CAP 64   // edge slots per node (deg ~ Poisson(16); P(deg>64) ~ 1e-18/node)

typedef unsigned long long ull;

// -------------------- device scratch --------------------
__device__ float g_A[(size_t)NN * 64];       // aggregation output (fp32)
__device__ float g_B[(size_t)NN * 64];       // raw layer outputs (fp32)
__device__ uint4 g_H[(size_t)NN * 8];        // activated features fp16
__device__ float g_xpad[(size_t)NN * 16];
__device__ int   g_cnt[NN];                  // per-node edge count (placement cursor)
__device__ int2  g_epack[(size_t)NN * CAP + 128];  // slotted (src, weight-bits) by dst
__device__ int   g_goff[GG + 1];
__device__ float g_stats[256];               // [0:128) layer0, [128:256) layer1

__device__ __forceinline__ void fma2(ull& d, ull a, ull b) {
    asm("fma.rn.f32x2 %0, %1, %2, %0;" : "+l"(d) : "l"(a), "l"(b));
}
__device__ __forceinline__ float2 unpack2(ull v) {
    float2 r; asm("mov.b64 {%0,%1}, %2;" : "=f"(r.x), "=f"(r.y) : "l"(v)); return r;
}
__device__ __forceinline__ ull pack2(float lo, float hi) {
    ull r; asm("mov.b64 %0, {%1,%2};" : "=l"(r) : "f"(lo), "f"(hi)); return r;
}

// -------------------- prep: xpad + graph bounds (no histogram needed) -----------
__global__ void prep(const float* __restrict__ x, float* __restrict__ xp,
                     const int* __restrict__ batch, int* __restrict__ goff) {
    int i = blockIdx.x * blockDim.x + threadIdx.x;
    if (i < NN * 16) { int n = i >> 4, c = i & 15; xp[i] = (c < 9) ? x[n * 9 + c] : 0.f; }
    if (i < NN) {
        int bi = batch[i];
        if (i == 0) { for (int g = 0; g <= bi; g++) goff[g] = 0; }
        else { int bp = batch[i - 1]; for (int g = bp + 1; g <= bi; g++) goff[g] = i; }
        if (i == NN - 1) { for (int g = bi + 1; g <= GG; g++) goff[g] = NN; }
    }
}

// -------------------- placement into fixed-capacity slots (no scan) -------------
__global__ void place_kernel(const int* __restrict__ src, const int* __restrict__ dst,
                             const float* __restrict__ ew, int* __restrict__ cnt,
                             int2* __restrict__ epack) {
    int e = blockIdx.x * blockDim.x + threadIdx.x;
    if (e >= EE) return;
    int d = dst[e];
    int p = atomicAdd(&cnt[d], 1);
    epack[((size_t)d << 6) + p] = make_int2(src[e], __float_as_int(ew[e]));
}

// -------------------- layer-0 CSR aggregation (fp32, unroll-4) ------------------
__global__ void __launch_bounds__(256) agg_csr4(
    const float* __restrict__ h, const int* __restrict__ cnt,
    const int2* __restrict__ epack, float* __restrict__ agg, float* __restrict__ stats) {
    if (blockIdx.x == 0) stats[threadIdx.x] = 0.f;   // zero both stats banks
    int node = blockIdx.x * 64 + (threadIdx.x >> 2);
    int lane = threadIdx.x & 3;
    if (node >= NN) return;
    int beg = node << 6, end = beg + cnt[node];
    float4 acc = make_float4(0.f, 0.f, 0.f, 0.f);
    int i = beg;
    for (; i + 3 < end; i += 4) {
        int2 e0 = epack[i], e1 = epack[i + 1], e2 = epack[i + 2], e3 = epack[i + 3];
        float4 v0 = ((const float4*)h)[(size_t)e0.x * 4 + lane];
        float4 v1 = ((const float4*)h)[(size_t)e1.x * 4 + lane];
        float4 v2 = ((const float4*)h)[(size_t)e2.x * 4 + lane];
        float4 v3 = ((const float4*)h)[(size_t)e3.x * 4 + lane];
        float w0 = __int_as_float(e0.y), w1 = __int_as_float(e1.y);
        float w2 = __int_as_float(e2.y), w3 = __int_as_float(e3.y);
        acc.x = fmaf(v0.x, w0, acc.x); acc.y = fmaf(v0.y, w0, acc.y);
        acc.z = fmaf(v0.z, w0, acc.z); acc.w = fmaf(v0.w, w0, acc.w);
        acc.x = fmaf(v1.x, w1, acc.x); acc.y = fmaf(v1.y, w1, acc.y);
        acc.z = fmaf(v1.z, w1, acc.z); acc.w = fmaf(v1.w, w1, acc.w);
        acc.x = fmaf(v2.x, w2, acc.x); acc.y = fmaf(v2.y, w2, acc.y);
        acc.z = fmaf(v2.z, w2, acc.z); acc.w = fmaf(v2.w, w2, acc.w);
        acc.x = fmaf(v3.x, w3, acc.x); acc.y = fmaf(v3.y, w3, acc.y);
        acc.z = fmaf(v3.z, w3, acc.z); acc.w = fmaf(v3.w, w3, acc.w);
    }
    for (; i < end; ++i) {
        int2 ep = epack[i];
        float w = __int_as_float(ep.y);
        float4 v = ((const float4*)h)[(size_t)ep.x * 4 + lane];
        acc.x = fmaf(v.x, w, acc.x); acc.y = fmaf(v.y, w, acc.y);
        acc.z = fmaf(v.z, w, acc.z); acc.w = fmaf(v.w, w, acc.w);
    }
    ((float4*)agg)[(size_t)node * 4 + lane] = acc;
}

// -------------------- fp16 CSR aggregation (unroll-4) --------------------
__device__ __forceinline__ void accum8(float* acc, uint4 r, float w) {
    __half2* hp = (__half2*)&r;
#pragma unroll
    for (int j = 0; j < 4; j++) {
        float2 f = __half22float2(hp[j]);
        acc[2 * j]     = fmaf(f.x, w, acc[2 * j]);
        acc[2 * j + 1] = fmaf(f.y, w, acc[2 * j + 1]);
    }
}

__global__ void __launch_bounds__(256) agg_csr_h(
    const uint4* __restrict__ h, const int* __restrict__ cnt,
    const int2* __restrict__ epack, float* __restrict__ agg) {
    int node = blockIdx.x * 32 + (threadIdx.x >> 3);
    int lane = threadIdx.x & 7;
    if (node >= NN) return;
    int beg = node << 6, end = beg + cnt[node];
    float acc[8];
#pragma unroll
    for (int j = 0; j < 8; j++) acc[j] = 0.f;
    int i = beg;
    for (; i + 3 < end; i += 4) {
        int2 e0 = epack[i], e1 = epack[i + 1], e2 = epack[i + 2], e3 = epack[i + 3];
        uint4 r0 = h[(size_t)e0.x * 8 + lane];
        uint4 r1 = h[(size_t)e1.x * 8 + lane];
        uint4 r2 = h[(size_t)e2.x * 8 + lane];
        uint4 r3 = h[(size_t)e3.x * 8 + lane];
        accum8(acc, r0, __int_as_float(e0.y));
        accum8(acc, r1, __int_as_float(e1.y));
        accum8(acc, r2, __int_as_float(e2.y));
        accum8(acc, r3, __int_as_float(e3.y));
    }
    for (; i < end; ++i) {
        int2 e0 = epack[i];
        uint4 r0 = h[(size_t)e0.x * 8 + lane];
        accum8(acc, r0, __int_as_float(e0.y));
    }
    float* dstp = &agg[(size_t)node * 64 + lane * 8];
    *(float4*)dstp       = make_float4(acc[0], acc[1], acc[2], acc[3]);
    *(float4*)(dstp + 4) = make_float4(acc[4], acc[5], acc[6], acc[7]);
}

// -------------------- layer-0 node update (K=9, scalar) --------------------
__global__ void __launch_bounds__(128) node_update9(
    const float* __restrict__ Ag, const float* __restrict__ Xin,
    const float* __restrict__ Wrel, const float* __restrict__ Wroot,
    const float* __restrict__ bias, float* __restrict__ Out, float* stats) {
    constexpr int K = 9, PAD = 17, C4 = 4;
    extern __shared__ float sm[];
    float* sA   = sm;
    float* sX   = sA + 64 * PAD;
    float* sWr  = sX + 64 * PAD;
    float* sWo  = sWr + K * 64;
    float* sSum = sWo + K * 64;
    float* sSq  = sSum + 64;

    const int tid = threadIdx.x;
    const int base = blockIdx.x * 64;

    for (int i = tid; i < K * 16; i += 128) {
        ((float4*)sWr)[i] = ((const float4*)Wrel)[i];
        ((float4*)sWo)[i] = ((const float4*)Wroot)[i];
    }
    for (int i = tid; i < 64 * C4; i += 128) {
        int r = i / C4, c = i - r * C4;
        int n = base + r;
        float4 va = make_float4(0.f, 0.f, 0.f, 0.f), vx = va;
        if (n < NN) {
            va = *(const float4*)&Ag[(size_t)n * 16 + c * 4];
            vx = *(const float4*)&Xin[(size_t)n * 16 + c * 4];
        }
        int o = r * PAD + c * 4;
        sA[o] = va.x; sA[o + 1] = va.y; sA[o + 2] = va.z; sA[o + 3] = va.w;
        sX[o] = vx.x; sX[o + 1] = vx.y; sX[o + 2] = vx.z; sX[o + 3] = vx.w;
    }
    if (tid < 64) { sSum[tid] = 0.f; sSq[tid] = 0.f; }
    __syncthreads();

    const int fg = (tid & 7) * 8;
    const int ng = (tid >> 3) * 4;

    float acc[4][8];
#pragma unroll
    for (int i = 0; i < 4; i++)
#pragma unroll
        for (int j = 0; j < 8; j++) acc[i][j] = 0.f;

#pragma unroll
    for (int k = 0; k < K; ++k) {
        float a[4], xv[4];
#pragma unroll
        for (int i = 0; i < 4; i++) {
            a[i]  = sA[(ng + i) * PAD + k];
            xv[i] = sX[(ng + i) * PAD + k];
        }
        float wr[8], wo[8];
        *(float4*)&wr[0] = *(const float4*)&sWr[k * 64 + fg];
        *(float4*)&wr[4] = *(const float4*)&sWr[k * 64 + fg + 4];
        *(float4*)&wo[0] = *(const float4*)&sWo[k * 64 + fg];
        *(float4*)&wo[4] = *(const float4*)&sWo[k * 64 + fg + 4];
#pragma unroll
        for (int i = 0; i < 4; i++)
#pragma unroll
            for (int j = 0; j < 8; j++)
                acc[i][j] = fmaf(xv[i], wo[j], fmaf(a[i], wr[j], acc[i][j]));
    }

    float bz[8];
    *(float4*)&bz[0] = *(const float4*)&bias[fg];
    *(float4*)&bz[4] = *(const float4*)&bias[fg + 4];

    float s[8], q[8];
#pragma unroll
    for (int j = 0; j < 8; j++) { s[j] = 0.f; q[j] = 0.f; }

#pragma unroll
    for (int i = 0; i < 4; i++) {
        int n = base + ng + i;
        if (n < NN) {
            float o[8];
#pragma unroll
            for (int j = 0; j < 8; j++) o[j] = acc[i][j] + bz[j];
            *(float4*)&Out[(size_t)n * 64 + fg]     = make_float4(o[0], o[1], o[2], o[3]);
            *(float4*)&Out[(size_t)n * 64 + fg + 4] = make_float4(o[4], o[5], o[6], o[7]);
#pragma unroll
            for (int j = 0; j < 8; j++) { s[j] += o[j]; q[j] += o[j] * o[j]; }
        }
    }
#pragma unroll
    for (int j = 0; j < 8; j++) {
        atomicAdd(&sSum[fg + j], s[j]);
        atomicAdd(&sSq[fg + j], q[j]);
    }
    __syncthreads();
    if (tid < 64) {
        atomicAdd(&stats[tid], sSum[tid]);
        atomicAdd(&stats[64 + tid], sSq[tid]);
    }
}

// -------------------- f32x2 node update (K=64), fp16 Xin --------------------
__global__ void __launch_bounds__(128) node_update64(
    const float* __restrict__ Ag, const uint4* __restrict__ Xh,
    const float* __restrict__ Wrel, const float* __restrict__ Wroot,
    const float* __restrict__ bias, float* __restrict__ Out, float* stats) {
    constexpr int PAD = 66;
    extern __shared__ float sm[];
    float* sA   = sm;
    float* sX   = sA + 64 * PAD;
    ull*   sWr  = (ull*)(sX + 64 * PAD);
    ull*   sWo  = sWr + 32 * 64;
    float* sSum = (float*)(sWo + 32 * 64);
    float* sSq  = sSum + 64;

    const int tid = threadIdx.x;
    const int base = blockIdx.x * 64;

    for (int idx = tid; idx < 32 * 16; idx += 128) {
        int k2 = idx >> 4, c4 = idx & 15;
        float4 r0 = ((const float4*)Wrel)[(2 * k2) * 16 + c4];
        float4 r1 = ((const float4*)Wrel)[(2 * k2 + 1) * 16 + c4];
        ull* p = &sWr[k2 * 64 + c4 * 4];
        p[0] = pack2(r0.x, r1.x); p[1] = pack2(r0.y, r1.y);
        p[2] = pack2(r0.z, r1.z); p[3] = pack2(r0.w, r1.w);
        r0 = ((const float4*)Wroot)[(2 * k2) * 16 + c4];
        r1 = ((const float4*)Wroot)[(2 * k2 + 1) * 16 + c4];
        p = &sWo[k2 * 64 + c4 * 4];
        p[0] = pack2(r0.x, r1.x); p[1] = pack2(r0.y, r1.y);
        p[2] = pack2(r0.z, r1.z); p[3] = pack2(r0.w, r1.w);
    }
    for (int i = tid; i < 64 * 16; i += 128) {
        int r = i >> 4, c = i & 15;
        int n = base + r;
        float4 va = make_float4(0.f, 0.f, 0.f, 0.f);
        if (n < NN) va = *(const float4*)&Ag[(size_t)n * 64 + c * 4];
        int o = r * PAD + c * 4;
        sA[o] = va.x; sA[o + 1] = va.y; sA[o + 2] = va.z; sA[o + 3] = va.w;
    }
    for (int i = tid; i < 64 * 8; i += 128) {
        int r = i >> 3, c = i & 7;
        int n = base + r;
        uint4 v = make_uint4(0u, 0u, 0u, 0u);
        if (n < NN) v = Xh[(size_t)n * 8 + c];
        __half2* hp = (__half2*)&v;
        float* o = &sX[r * PAD + c * 8];
#pragma unroll
        for (int j = 0; j < 4; j++) {
            float2 f = __half22float2(hp[j]);
            o[2 * j] = f.x; o[2 * j + 1] = f.y;
        }
    }
    if (tid < 64) { sSum[tid] = 0.f; sSq[tid] = 0.f; }
    __syncthreads();

    const int f0 = (tid & 7) * 2;
    const int ng = (tid >> 3) * 4;

    ull acc2[4][8];
#pragma unroll
    for (int i = 0; i < 4; i++)
#pragma unroll
        for (int j = 0; j < 8; j++) acc2[i][j] = 0ull;

#pragma unroll 2
    for (int k2 = 0; k2 < 32; ++k2) {
        ull av[4], xv[4];
#pragma unroll
        for (int i = 0; i < 4; i++) {
            av[i] = *(const ull*)&sA[(ng + i) * PAD + 2 * k2];
            xv[i] = *(const ull*)&sX[(ng + i) * PAD + 2 * k2];
        }
#pragma unroll
        for (int c = 0; c < 4; c++) {
            ulonglong2 wr = *(const ulonglong2*)&sWr[k2 * 64 + f0 + 16 * c];
            ulonglong2 wo = *(const ulonglong2*)&sWo[k2 * 64 + f0 + 16 * c];
#pragma unroll
            for (int i = 0; i < 4; i++) {
                fma2(acc2[i][2 * c],     av[i], wr.x);
                fma2(acc2[i][2 * c + 1], av[i], wr.y);
                fma2(acc2[i][2 * c],     xv[i], wo.x);
                fma2(acc2[i][2 * c + 1], xv[i], wo.y);
            }
        }
    }

    float bz[8];
#pragma unroll
    for (int c = 0; c < 4; c++) {
        float2 b2 = *(const float2*)&bias[f0 + 16 * c];
        bz[2 * c] = b2.x; bz[2 * c + 1] = b2.y;
    }

    float s[8], q[8];
#pragma unroll
    for (int j = 0; j < 8; j++) { s[j] = 0.f; q[j] = 0.f; }

#pragma unroll
    for (int i = 0; i < 4; i++) {
        int n = base + ng + i;
        if (n < NN) {
#pragma unroll
            for (int c = 0; c < 4; c++) {
                float2 e0 = unpack2(acc2[i][2 * c]);
                float2 e1 = unpack2(acc2[i][2 * c + 1]);
                float o0 = e0.x + e0.y + bz[2 * c];
                float o1 = e1.x + e1.y + bz[2 * c + 1];
                *(float2*)&Out[(size_t)n * 64 + f0 + 16 * c] = make_float2(o0, o1);
                s[2 * c] += o0; q[2 * c] += o0 * o0;
                s[2 * c + 1] += o1; q[2 * c + 1] += o1 * o1;
            }
        }
    }
#pragma unroll
    for (int c = 0; c < 4; c++) {
        atomicAdd(&sSum[f0 + 16 * c],     s[2 * c]);
        atomicAdd(&sSum[f0 + 16 * c + 1], s[2 * c + 1]);
        atomicAdd(&sSq[f0 + 16 * c],      q[2 * c]);
        atomicAdd(&sSq[f0 + 16 * c + 1],  q[2 * c + 1]);
    }
    __syncthreads();
    if (tid < 64) {
        atomicAdd(&stats[tid], sSum[tid]);
        atomicAdd(&stats[64 + tid], sSq[tid]);
    }
}

// -------------------- BN finalize + apply + ReLU + fp16 convert (fused) --------
__global__ void __launch_bounds__(256) bn_act_h(
    const float* __restrict__ in, const float* __restrict__ stats,
    const float* __restrict__ g, const float* __restrict__ be,
    uint4* __restrict__ outh) {
    __shared__ float sc[64], sh[64];
    if (threadIdx.x < 64) {
        int f = threadIdx.x;
        const float inv = 1.f / (float)NN;
        float m = stats[f] * inv;
        float var = stats[64 + f] * inv - m * m;
        float s = g[f] * rsqrtf(var + 1e-5f);
        sc[f] = s;
        sh[f] = fmaf(-m, s, be[f]);
    }
    __syncthreads();
    int i = blockIdx.x * blockDim.x + threadIdx.x;
    if (i >= NN * 8) return;
    int c8 = (i & 7) * 8;
    float4 a = ((const float4*)in)[2 * i];
    float4 b = ((const float4*)in)[2 * i + 1];
    a.x = fmaxf(fmaf(a.x, sc[c8 + 0], sh[c8 + 0]), 0.f);
    a.y = fmaxf(fmaf(a.y, sc[c8 + 1], sh[c8 + 1]), 0.f);
    a.z = fmaxf(fmaf(a.z, sc[c8 + 2], sh[c8 + 2]), 0.f);
    a.w = fmaxf(fmaf(a.w, sc[c8 + 3], sh[c8 + 3]), 0.f);
    b.x = fmaxf(fmaf(b.x, sc[c8 + 4], sh[c8 + 4]), 0.f);
    b.y = fmaxf(fmaf(b.y, sc[c8 + 5], sh[c8 + 5]), 0.f);
    b.z = fmaxf(fmaf(b.z, sc[c8 + 6], sh[c8 + 6]), 0.f);
    b.w = fmaxf(fmaf(b.w, sc[c8 + 7], sh[c8 + 7]), 0.f);
    __half2 h0 = __floats2half2_rn(a.x, a.y);
    __half2 h1 = __floats2half2_rn(a.z, a.w);
    __half2 h2 = __floats2half2_rn(b.x, b.y);
    __half2 h3 = __floats2half2_rn(b.z, b.w);
    uint4 o;
    o.x = *(unsigned*)&h0; o.y = *(unsigned*)&h1;
    o.z = *(unsigned*)&h2; o.w = *(unsigned*)&h3;
    outh[i] = o;
}

// -------------------- layer-2 pooled GEMM + MLP head --------------------
__global__ void pool2_head(const float* __restrict__ Ag, const uint4* __restrict__ Xh,
                           const float* __restrict__ W2rel, const float* __restrict__ W2root,
                           const float* __restrict__ b2, const int* __restrict__ goff,
                           const float* __restrict__ Wl1, const float* __restrict__ bl1,
                           const float* __restrict__ Wl2, const float* __restrict__ bl2,
                           float* __restrict__ out) {
    __shared__ float sAg[64], sXp[64], sPool[64], sz[64];
    int g = blockIdx.x, t = threadIdx.x;
    int beg = goff[g], end = goff[g + 1];
    const __half* xh = (const __half*)Xh;
    float sa = 0.f, sx = 0.f;
    for (int n = beg; n < end; ++n) {
        sa += Ag[(size_t)n * 64 + t];
        sx += __half2float(xh[(size_t)n * 64 + t]);
    }
    sAg[t] = sa; sXp[t] = sx;
    __syncthreads();
    float cnt = (float)(end - beg);
    float acc = cnt * b2[t];
#pragma unroll 8
    for (int k = 0; k < 64; k++)
        acc += sAg[k] * W2rel[k * 64 + t] + sXp[k] * W2root[k * 64 + t];
    sPool[t] = acc / fmaxf(cnt, 1.f);
    __syncthreads();
    float z = bl1[t];
#pragma unroll 8
    for (int k = 0; k < 64; k++) z = fmaf(sPool[k], Wl1[k * 64 + t], z);
    sz[t] = fmaxf(z, 0.f);
    __syncthreads();
    if (t < 6) {
        float o = bl2[t];
#pragma unroll 8
        for (int k = 0; k < 64; k++) o = fmaf(sz[k], Wl2[k * 6 + t], o);
        out[g * 6 + t] = o;
    }
}

// -------------------- launch --------------------
extern "C" void kernel_launch(void* const* d_in, const int* in_sizes, int n_in,
                              void* d_out, int out_size) {
    const float* x     = (const float*)d_in[0];
    const int*   ei    = (const int*)d_in[1];
    const float* ew    = (const float*)d_in[2];
    const int*   batch = (const int*)d_in[3];
    const float *Wrel0 = (const float*)d_in[4],  *Wroot0 = (const float*)d_in[5],  *b0 = (const float*)d_in[6];
    const float *Wrel1 = (const float*)d_in[7],  *Wroot1 = (const float*)d_in[8],  *b1 = (const float*)d_in[9];
    const float *Wrel2 = (const float*)d_in[10], *Wroot2 = (const float*)d_in[11], *b2 = (const float*)d_in[12];
    const float *g0 = (const float*)d_in[13], *be0 = (const float*)d_in[14];
    const float *g1 = (const float*)d_in[15], *be1 = (const float*)d_in[16];
    const float *Wl1 = (const float*)d_in[17], *bl1 = (const float*)d_in[18];
    const float *Wl2 = (const float*)d_in[19], *bl2 = (const float*)d_in[20];
    float* out = (float*)d_out;

    const int* src = ei;
    const int* dst = ei + EE;

    float *pA, *pB, *pX, *pStats;
    uint4* pH;
    int *pCnt, *pGoff;
    int2* pEpack;
    cudaGetSymbolAddress((void**)&pA, g_A);
    cudaGetSymbolAddress((void**)&pB, g_B);
    cudaGetSymbolAddress((void**)&pH, g_H);
    cudaGetSymbolAddress((void**)&pX, g_xpad);
    cudaGetSymbolAddress((void**)&pStats, g_stats);
    cudaGetSymbolAddress((void**)&pCnt, g_cnt);
    cudaGetSymbolAddress((void**)&pGoff, g_goff);
    cudaGetSymbolAddress((void**)&pEpack, g_epack);

    const int smem64 = 64 * 66 * 4 * 2 + 32 * 64 * 8 * 2 + 128 * 4;  // 67072 B
    const int smem9  = (64 * 17 * 2 + 9 * 64 * 2 + 128) * (int)sizeof(float);
    cudaFuncSetAttribute((const void*)node_update64,
                         cudaFuncAttributeMaxDynamicSharedMemorySize, smem64);

    const int NB = (NN + 63) / 64;

    // ---- slotted CSR build (no histogram, no scan) ----
    cudaMemsetAsync(pCnt, 0, NN * sizeof(int));
    prep<<<(NN * 16 + 255) / 256, 256>>>(x, pX, batch, pGoff);
    place_kernel<<<(EE + 511) / 512, 512>>>(src, dst, ew, pCnt, pEpack);

    // ---- layer 0 ----
    agg_csr4<<<(NN + 63) / 64, 256>>>(pX, pCnt, pEpack, pA, pStats);
    node_update9<<<NB, 128, smem9>>>(pA, pX, Wrel0, Wroot0, b0, pB, pStats);
    bn_act_h<<<(NN * 8 + 255) / 256, 256>>>(pB, pStats, g0, be0, pH);

    // ---- layer 1 ----
    agg_csr_h<<<(NN + 31) / 32, 256>>>(pH, pCnt, pEpack, pA);
    node_update64<<<NB, 128, smem64>>>(pA, pH, Wrel1, Wroot1, b1, pB, pStats + 128);
    bn_act_h<<<(NN * 8 + 255) / 256, 256>>>(pB, pStats + 128, g1, be1, pH);

    // ---- layer 2: gather then pooled GEMM + head ----
    agg_csr_h<<<(NN + 31) / 32, 256>>>(pH, pCnt, pEpack, pA);
    pool2_head<<<GG, 64>>>(pA, pH, Wrel2, Wroot2, b2, pGoff, Wl1, bl1, Wl2, bl2, out);
}

// round 12
// speedup vs baseline: 1.0679x; 1.0328x over previous
#include <cuda_runtime.h>
#include <cuda_fp16.h>

#define NN 100000
#define EE 1600000
#define GG 1024
#define CAP 64

typedef unsigned long long ull;

// -------------------- device scratch --------------------
__device__ float g_A[(size_t)NN * 64];       // aggregation output (fp32)
__device__ uint4 g_B[(size_t)NN * 8];        // raw layer outputs (fp16: 64 halves = 8 uint4/node)
__device__ uint4 g_H[(size_t)NN * 8];        // activated features fp16
__device__ float g_xpad[(size_t)NN * 16];
__device__ int   g_cnt[NN];
__device__ int2  g_epack[(size_t)NN * CAP + 128];
__device__ int   g_goff[GG + 1];
__device__ float g_stats[256];

__device__ __forceinline__ void fma2(ull& d, ull a, ull b) {
    asm("fma.rn.f32x2 %0, %1, %2, %0;" : "+l"(d) : "l"(a), "l"(b));
}
__device__ __forceinline__ float2 unpack2(ull v) {
    float2 r; asm("mov.b64 {%0,%1}, %2;" : "=f"(r.x), "=f"(r.y) : "l"(v)); return r;
}
__device__ __forceinline__ ull pack2(float lo, float hi) {
    ull r; asm("mov.b64 %0, {%1,%2};" : "=l"(r) : "f"(lo), "f"(hi)); return r;
}
__device__ __forceinline__ ull rep2(float v) {
    ull r; asm("mov.b64 %0, {%1,%1};" : "=l"(r) : "f"(v)); return r;
}

// -------------------- fused placement + xpad + graph bounds ---------------------
// EE == NN*16 == 1.6M: one grid covers all three index spaces.
__global__ void place_prep(const int* __restrict__ src, const int* __restrict__ dst,
                           const float* __restrict__ ew, int* __restrict__ cnt,
                           int2* __restrict__ epack,
                           const float* __restrict__ x, float* __restrict__ xp,
                           const int* __restrict__ batch, int* __restrict__ goff) {
    int e = blockIdx.x * blockDim.x + threadIdx.x;
    if (e < EE) {
        int d = dst[e];
        int p = atomicAdd(&cnt[d], 1);
        epack[((size_t)d << 6) + p] = make_int2(src[e], __float_as_int(ew[e]));
    }
    if (e < NN * 16) { int n = e >> 4, c = e & 15; xp[e] = (c < 9) ? x[n * 9 + c] : 0.f; }
    if (e < NN) {
        int bi = batch[e];
        if (e == 0) { for (int g = 0; g <= bi; g++) goff[g] = 0; }
        else { int bp = batch[e - 1]; for (int g = bp + 1; g <= bi; g++) goff[g] = e; }
        if (e == NN - 1) { for (int g = bi + 1; g <= GG; g++) goff[g] = NN; }
    }
}

// -------------------- layer-0 aggregation (fp32, unroll-4) ----------------------
__global__ void __launch_bounds__(256) agg_csr4(
    const float* __restrict__ h, const int* __restrict__ cnt,
    const int2* __restrict__ epack, float* __restrict__ agg, float* __restrict__ stats) {
    if (blockIdx.x == 0) stats[threadIdx.x] = 0.f;
    int node = blockIdx.x * 64 + (threadIdx.x >> 2);
    int lane = threadIdx.x & 3;
    if (node >= NN) return;
    int beg = node << 6, end = beg + cnt[node];
    float4 acc = make_float4(0.f, 0.f, 0.f, 0.f);
    int i = beg;
    for (; i + 3 < end; i += 4) {
        int2 e0 = epack[i], e1 = epack[i + 1], e2 = epack[i + 2], e3 = epack[i + 3];
        float4 v0 = ((const float4*)h)[(size_t)e0.x * 4 + lane];
        float4 v1 = ((const float4*)h)[(size_t)e1.x * 4 + lane];
        float4 v2 = ((const float4*)h)[(size_t)e2.x * 4 + lane];
        float4 v3 = ((const float4*)h)[(size_t)e3.x * 4 + lane];
        float w0 = __int_as_float(e0.y), w1 = __int_as_float(e1.y);
        float w2 = __int_as_float(e2.y), w3 = __int_as_float(e3.y);
        acc.x = fmaf(v0.x, w0, acc.x); acc.y = fmaf(v0.y, w0, acc.y);
        acc.z = fmaf(v0.z, w0, acc.z); acc.w = fmaf(v0.w, w0, acc.w);
        acc.x = fmaf(v1.x, w1, acc.x); acc.y = fmaf(v1.y, w1, acc.y);
        acc.z = fmaf(v1.z, w1, acc.z); acc.w = fmaf(v1.w, w1, acc.w);
        acc.x = fmaf(v2.x, w2, acc.x); acc.y = fmaf(v2.y, w2, acc.y);
        acc.z = fmaf(v2.z, w2, acc.z); acc.w = fmaf(v2.w, w2, acc.w);
        acc.x = fmaf(v3.x, w3, acc.x); acc.y = fmaf(v3.y, w3, acc.y);
        acc.z = fmaf(v3.z, w3, acc.z); acc.w = fmaf(v3.w, w3, acc.w);
    }
    for (; i < end; ++i) {
        int2 ep = epack[i];
        float w = __int_as_float(ep.y);
        float4 v = ((const float4*)h)[(size_t)ep.x * 4 + lane];
        acc.x = fmaf(v.x, w, acc.x); acc.y = fmaf(v.y, w, acc.y);
        acc.z = fmaf(v.z, w, acc.z); acc.w = fmaf(v.w, w, acc.w);
    }
    ((float4*)agg)[(size_t)node * 4 + lane] = acc;
}

// -------------------- fp16 aggregation (unroll-4) --------------------
__device__ __forceinline__ void accum8(float* acc, uint4 r, float w) {
    __half2* hp = (__half2*)&r;
#pragma unroll
    for (int j = 0; j < 4; j++) {
        float2 f = __half22float2(hp[j]);
        acc[2 * j]     = fmaf(f.x, w, acc[2 * j]);
        acc[2 * j + 1] = fmaf(f.y, w, acc[2 * j + 1]);
    }
}

__global__ void __launch_bounds__(256) agg_csr_h(
    const uint4* __restrict__ h, const int* __restrict__ cnt,
    const int2* __restrict__ epack, float* __restrict__ agg) {
    int node = blockIdx.x * 32 + (threadIdx.x >> 3);
    int lane = threadIdx.x & 7;
    if (node >= NN) return;
    int beg = node << 6, end = beg + cnt[node];
    float acc[8];
#pragma unroll
    for (int j = 0; j < 8; j++) acc[j] = 0.f;
    int i = beg;
    for (; i + 3 < end; i += 4) {
        int2 e0 = epack[i], e1 = epack[i + 1], e2 = epack[i + 2], e3 = epack[i + 3];
        uint4 r0 = h[(size_t)e0.x * 8 + lane];
        uint4 r1 = h[(size_t)e1.x * 8 + lane];
        uint4 r2 = h[(size_t)e2.x * 8 + lane];
        uint4 r3 = h[(size_t)e3.x * 8 + lane];
        accum8(acc, r0, __int_as_float(e0.y));
        accum8(acc, r1, __int_as_float(e1.y));
        accum8(acc, r2, __int_as_float(e2.y));
        accum8(acc, r3, __int_as_float(e3.y));
    }
    for (; i < end; ++i) {
        int2 e0 = epack[i];
        uint4 r0 = h[(size_t)e0.x * 8 + lane];
        accum8(acc, r0, __int_as_float(e0.y));
    }
    float* dstp = &agg[(size_t)node * 64 + lane * 8];
    *(float4*)dstp       = make_float4(acc[0], acc[1], acc[2], acc[3]);
    *(float4*)(dstp + 4) = make_float4(acc[4], acc[5], acc[6], acc[7]);
}

// -------------------- layer-0 node update (K=9, f32x2 feature pairs, fp16 out) --
__global__ void __launch_bounds__(128) node_update9(
    const float* __restrict__ Ag, const float* __restrict__ Xin,
    const float* __restrict__ Wrel, const float* __restrict__ Wroot,
    const float* __restrict__ bias, uint4* __restrict__ Outh, float* stats) {
    constexpr int K = 9, PAD = 18;
    extern __shared__ float sm[];
    float* sA   = sm;                // 64*18
    float* sX   = sA + 64 * PAD;     // 64*18
    float* sWr  = sX + 64 * PAD;     // 9*64
    float* sWo  = sWr + K * 64;      // 9*64
    float* sSum = sWo + K * 64;
    float* sSq  = sSum + 64;

    const int tid = threadIdx.x;
    const int base = blockIdx.x * 64;

    for (int i = tid; i < K * 16; i += 128) {
        ((float4*)sWr)[i] = ((const float4*)Wrel)[i];
        ((float4*)sWo)[i] = ((const float4*)Wroot)[i];
    }
    for (int i = tid; i < 64 * 4; i += 128) {
        int r = i >> 2, c = i & 3;
        int n = base + r;
        float4 va = make_float4(0.f, 0.f, 0.f, 0.f), vx = va;
        if (n < NN) {
            va = *(const float4*)&Ag[(size_t)n * 16 + c * 4];
            vx = *(const float4*)&Xin[(size_t)n * 16 + c * 4];
        }
        ull* pa = (ull*)&sA[r * PAD + c * 4];   // r*18+c*4 even -> 8B aligned
        ull* px = (ull*)&sX[r * PAD + c * 4];
        pa[0] = pack2(va.x, va.y); pa[1] = pack2(va.z, va.w);
        px[0] = pack2(vx.x, vx.y); px[1] = pack2(vx.z, vx.w);
    }
    if (tid < 64) { sSum[tid] = 0.f; sSq[tid] = 0.f; }
    __syncthreads();

    const int f0 = (tid & 7) * 8;    // 8 consecutive features = 4 f32x2 pairs
    const int ng = (tid >> 3) * 4;   // 4 nodes

    ull acc2[4][4];
#pragma unroll
    for (int i = 0; i < 4; i++)
#pragma unroll
        for (int p = 0; p < 4; p++) acc2[i][p] = 0ull;

#pragma unroll
    for (int k = 0; k < K; ++k) {
        ull ra[4], rx[4];
#pragma unroll
        for (int i = 0; i < 4; i++) {
            ra[i] = rep2(sA[(ng + i) * PAD + k]);
            rx[i] = rep2(sX[(ng + i) * PAD + k]);
        }
        ulonglong2 wr0 = *(const ulonglong2*)&sWr[k * 64 + f0];
        ulonglong2 wr1 = *(const ulonglong2*)&sWr[k * 64 + f0 + 4];
        ulonglong2 wo0 = *(const ulonglong2*)&sWo[k * 64 + f0];
        ulonglong2 wo1 = *(const ulonglong2*)&sWo[k * 64 + f0 + 4];
#pragma unroll
        for (int i = 0; i < 4; i++) {
            fma2(acc2[i][0], ra[i], wr0.x);
            fma2(acc2[i][1], ra[i], wr0.y);
            fma2(acc2[i][2], ra[i], wr1.x);
            fma2(acc2[i][3], ra[i], wr1.y);
            fma2(acc2[i][0], rx[i], wo0.x);
            fma2(acc2[i][1], rx[i], wo0.y);
            fma2(acc2[i][2], rx[i], wo1.x);
            fma2(acc2[i][3], rx[i], wo1.y);
        }
    }

    float bz[8];
    *(float4*)&bz[0] = *(const float4*)&bias[f0];
    *(float4*)&bz[4] = *(const float4*)&bias[f0 + 4];

    float s[8], q[8];
#pragma unroll
    for (int j = 0; j < 8; j++) { s[j] = 0.f; q[j] = 0.f; }

#pragma unroll
    for (int i = 0; i < 4; i++) {
        int n = base + ng + i;
        if (n < NN) {
            float o[8];
#pragma unroll
            for (int p = 0; p < 4; p++) {
                float2 v = unpack2(acc2[i][p]);
                o[2 * p]     = v.x + bz[2 * p];
                o[2 * p + 1] = v.y + bz[2 * p + 1];
            }
            __half2 h0 = __floats2half2_rn(o[0], o[1]);
            __half2 h1 = __floats2half2_rn(o[2], o[3]);
            __half2 h2 = __floats2half2_rn(o[4], o[5]);
            __half2 h3 = __floats2half2_rn(o[6], o[7]);
            uint4 ov;
            ov.x = *(unsigned*)&h0; ov.y = *(unsigned*)&h1;
            ov.z = *(unsigned*)&h2; ov.w = *(unsigned*)&h3;
            Outh[(size_t)n * 8 + (tid & 7)] = ov;
#pragma unroll
            for (int j = 0; j < 8; j++) { s[j] += o[j]; q[j] += o[j] * o[j]; }
        }
    }
#pragma unroll
    for (int j = 0; j < 8; j++) {
        atomicAdd(&sSum[f0 + j], s[j]);
        atomicAdd(&sSq[f0 + j], q[j]);
    }
    __syncthreads();
    if (tid < 64) {
        atomicAdd(&stats[tid], sSum[tid]);
        atomicAdd(&stats[64 + tid], sSq[tid]);
    }
}

// -------------------- f32x2 node update (K=64), fp16 Xin, fp16 out --------------
__global__ void __launch_bounds__(128) node_update64(
    const float* __restrict__ Ag, const uint4* __restrict__ Xh,
    const float* __restrict__ Wrel, const float* __restrict__ Wroot,
    const float* __restrict__ bias, __half* __restrict__ Outh, float* stats) {
    constexpr int PAD = 66;
    extern __shared__ float sm[];
    float* sA   = sm;
    float* sX   = sA + 64 * PAD;
    ull*   sWr  = (ull*)(sX + 64 * PAD);
    ull*   sWo  = sWr + 32 * 64;
    float* sSum = (float*)(sWo + 32 * 64);
    float* sSq  = sSum + 64;

    const int tid = threadIdx.x;
    const int base = blockIdx.x * 64;

    for (int idx = tid; idx < 32 * 16; idx += 128) {
        int k2 = idx >> 4, c4 = idx & 15;
        float4 r0 = ((const float4*)Wrel)[(2 * k2) * 16 + c4];
        float4 r1 = ((const float4*)Wrel)[(2 * k2 + 1) * 16 + c4];
        ull* p = &sWr[k2 * 64 + c4 * 4];
        p[0] = pack2(r0.x, r1.x); p[1] = pack2(r0.y, r1.y);
        p[2] = pack2(r0.z, r1.z); p[3] = pack2(r0.w, r1.w);
        r0 = ((const float4*)Wroot)[(2 * k2) * 16 + c4];
        r1 = ((const float4*)Wroot)[(2 * k2 + 1) * 16 + c4];
        p = &sWo[k2 * 64 + c4 * 4];
        p[0] = pack2(r0.x, r1.x); p[1] = pack2(r0.y, r1.y);
        p[2] = pack2(r0.z, r1.z); p[3] = pack2(r0.w, r1.w);
    }
    for (int i = tid; i < 64 * 16; i += 128) {
        int r = i >> 4, c = i & 15;
        int n = base + r;
        float4 va = make_float4(0.f, 0.f, 0.f, 0.f);
        if (n < NN) va = *(const float4*)&Ag[(size_t)n * 64 + c * 4];
        int o = r * PAD + c * 4;
        sA[o] = va.x; sA[o + 1] = va.y; sA[o + 2] = va.z; sA[o + 3] = va.w;
    }
    for (int i = tid; i < 64 * 8; i += 128) {
        int r = i >> 3, c = i & 7;
        int n = base + r;
        uint4 v = make_uint4(0u, 0u, 0u, 0u);
        if (n < NN) v = Xh[(size_t)n * 8 + c];
        __half2* hp = (__half2*)&v;
        float* o = &sX[r * PAD + c * 8];
#pragma unroll
        for (int j = 0; j < 4; j++) {
            float2 f = __half22float2(hp[j]);
            o[2 * j] = f.x; o[2 * j + 1] = f.y;
        }
    }
    if (tid < 64) { sSum[tid] = 0.f; sSq[tid] = 0.f; }
    __syncthreads();

    const int f0 = (tid & 7) * 2;
    const int ng = (tid >> 3) * 4;

    ull acc2[4][8];
#pragma unroll
    for (int i = 0; i < 4; i++)
#pragma unroll
        for (int j = 0; j < 8; j++) acc2[i][j] = 0ull;

#pragma unroll 2
    for (int k2 = 0; k2 < 32; ++k2) {
        ull av[4], xv[4];
#pragma unroll
        for (int i = 0; i < 4; i++) {
            av[i] = *(const ull*)&sA[(ng + i) * PAD + 2 * k2];
            xv[i] = *(const ull*)&sX[(ng + i) * PAD + 2 * k2];
        }
#pragma unroll
        for (int c = 0; c < 4; c++) {
            ulonglong2 wr = *(const ulonglong2*)&sWr[k2 * 64 + f0 + 16 * c];
            ulonglong2 wo = *(const ulonglong2*)&sWo[k2 * 64 + f0 + 16 * c];
#pragma unroll
            for (int i = 0; i < 4; i++) {
                fma2(acc2[i][2 * c],     av[i], wr.x);
                fma2(acc2[i][2 * c + 1], av[i], wr.y);
                fma2(acc2[i][2 * c],     xv[i], wo.x);
                fma2(acc2[i][2 * c + 1], xv[i], wo.y);
            }
        }
    }

    float bz[8];
#pragma unroll
    for (int c = 0; c < 4; c++) {
        float2 b2 = *(const float2*)&bias[f0 + 16 * c];
        bz[2 * c] = b2.x; bz[2 * c + 1] = b2.y;
    }

    float s[8], q[8];
#pragma unroll
    for (int j = 0; j < 8; j++) { s[j] = 0.f; q[j] = 0.f; }

#pragma unroll
    for (int i = 0; i < 4; i++) {
        int n = base + ng + i;
        if (n < NN) {
#pragma unroll
            for (int c = 0; c < 4; c++) {
                float2 e0 = unpack2(acc2[i][2 * c]);
                float2 e1 = unpack2(acc2[i][2 * c + 1]);
                float o0 = e0.x + e0.y + bz[2 * c];
                float o1 = e1.x + e1.y + bz[2 * c + 1];
                __half2 hv = __floats2half2_rn(o0, o1);
                *(__half2*)&Outh[(size_t)n * 64 + f0 + 16 * c] = hv;
                s[2 * c] += o0; q[2 * c] += o0 * o0;
                s[2 * c + 1] += o1; q[2 * c + 1] += o1 * o1;
            }
        }
    }
#pragma unroll
    for (int c = 0; c < 4; c++) {
        atomicAdd(&sSum[f0 + 16 * c],     s[2 * c]);
        atomicAdd(&sSum[f0 + 16 * c + 1], s[2 * c + 1]);
        atomicAdd(&sSq[f0 + 16 * c],      q[2 * c]);
        atomicAdd(&sSq[f0 + 16 * c + 1],  q[2 * c + 1]);
    }
    __syncthreads();
    if (tid < 64) {
        atomicAdd(&stats[tid], sSum[tid]);
        atomicAdd(&stats[64 + tid], sSq[tid]);
    }
}

// -------------------- BN finalize + apply + ReLU (fp16 in, fp16 out) -----------
__global__ void __launch_bounds__(256) bn_act_h(
    const uint4* __restrict__ inh, const float* __restrict__ stats,
    const float* __restrict__ g, const float* __restrict__ be,
    uint4* __restrict__ outh) {
    __shared__ float sc[64], sh[64];
    if (threadIdx.x < 64) {
        int f = threadIdx.x;
        const float inv = 1.f / (float)NN;
        float m = stats[f] * inv;
        float var = stats[64 + f] * inv - m * m;
        float s = g[f] * rsqrtf(var + 1e-5f);
        sc[f] = s;
        sh[f] = fmaf(-m, s, be[f]);
    }
    __syncthreads();
    int i = blockIdx.x * blockDim.x + threadIdx.x;
    if (i >= NN * 8) return;
    int c8 = (i & 7) * 8;
    uint4 v = inh[i];
    __half2* hp = (__half2*)&v;
    float o[8];
#pragma unroll
    for (int j = 0; j < 4; j++) {
        float2 f = __half22float2(hp[j]);
        o[2 * j]     = fmaxf(fmaf(f.x, sc[c8 + 2 * j],     sh[c8 + 2 * j]), 0.f);
        o[2 * j + 1] = fmaxf(fmaf(f.y, sc[c8 + 2 * j + 1], sh[c8 + 2 * j + 1]), 0.f);
    }
    __half2 h0 = __floats2half2_rn(o[0], o[1]);
    __half2 h1 = __floats2half2_rn(o[2], o[3]);
    __half2 h2 = __floats2half2_rn(o[4], o[5]);
    __half2 h3 = __floats2half2_rn(o[6], o[7]);
    uint4 ov;
    ov.x = *(unsigned*)&h0; ov.y = *(unsigned*)&h1;
    ov.z = *(unsigned*)&h2; ov.w = *(unsigned*)&h3;
    outh[i] = ov;
}

// -------------------- layer-2 pooled GEMM + MLP head --------------------
__global__ void pool2_head(const float* __restrict__ Ag, const uint4* __restrict__ Xh,
                           const float* __restrict__ W2rel, const float* __restrict__ W2root,
                           const float* __restrict__ b2, const int* __restrict__ goff,
                           const float* __restrict__ Wl1, const float* __restrict__ bl1,
                           const float* __restrict__ Wl2, const float* __restrict__ bl2,
                           float* __restrict__ out) {
    __shared__ float sAg[64], sXp[64], sPool[64], sz[64];
    int g = blockIdx.x, t = threadIdx.x;
    int beg = goff[g], end = goff[g + 1];
    const __half* xh = (const __half*)Xh;
    float sa = 0.f, sx = 0.f;
    for (int n = beg; n < end; ++n) {
        sa += Ag[(size_t)n * 64 + t];
        sx += __half2float(xh[(size_t)n * 64 + t]);
    }
    sAg[t] = sa; sXp[t] = sx;
    __syncthreads();
    float cnt = (float)(end - beg);
    float acc = cnt * b2[t];
#pragma unroll 8
    for (int k = 0; k < 64; k++)
        acc += sAg[k] * W2rel[k * 64 + t] + sXp[k] * W2root[k * 64 + t];
    sPool[t] = acc / fmaxf(cnt, 1.f);
    __syncthreads();
    float z = bl1[t];
#pragma unroll 8
    for (int k = 0; k < 64; k++) z = fmaf(sPool[k], Wl1[k * 64 + t], z);
    sz[t] = fmaxf(z, 0.f);
    __syncthreads();
    if (t < 6) {
        float o = bl2[t];
#pragma unroll 8
        for (int k = 0; k < 64; k++) o = fmaf(sz[k], Wl2[k * 6 + t], o);
        out[g * 6 + t] = o;
    }
}

// -------------------- launch --------------------
extern "C" void kernel_launch(void* const* d_in, const int* in_sizes, int n_in,
                              void* d_out, int out_size) {
    const float* x     = (const float*)d_in[0];
    const int*   ei    = (const int*)d_in[1];
    const float* ew    = (const float*)d_in[2];
    const int*   batch = (const int*)d_in[3];
    const float *Wrel0 = (const float*)d_in[4],  *Wroot0 = (const float*)d_in[5],  *b0 = (const float*)d_in[6];
    const float *Wrel1 = (const float*)d_in[7],  *Wroot1 = (const float*)d_in[8],  *b1 = (const float*)d_in[9];
    const float *Wrel2 = (const float*)d_in[10], *Wroot2 = (const float*)d_in[11], *b2 = (const float*)d_in[12];
    const float *g0 = (const float*)d_in[13], *be0 = (const float*)d_in[14];
    const float *g1 = (const float*)d_in[15], *be1 = (const float*)d_in[16];
    const float *Wl1 = (const float*)d_in[17], *bl1 = (const float*)d_in[18];
    const float *Wl2 = (const float*)d_in[19], *bl2 = (const float*)d_in[20];
    float* out = (float*)d_out;

    const int* src = ei;
    const int* dst = ei + EE;

    float *pA, *pX, *pStats;
    uint4 *pB, *pH;
    int *pCnt, *pGoff;
    int2* pEpack;
    cudaGetSymbolAddress((void**)&pA, g_A);
    cudaGetSymbolAddress((void**)&pB, g_B);
    cudaGetSymbolAddress((void**)&pH, g_H);
    cudaGetSymbolAddress((void**)&pX, g_xpad);
    cudaGetSymbolAddress((void**)&pStats, g_stats);
    cudaGetSymbolAddress((void**)&pCnt, g_cnt);
    cudaGetSymbolAddress((void**)&pGoff, g_goff);
    cudaGetSymbolAddress((void**)&pEpack, g_epack);

    const int smem64 = 64 * 66 * 4 * 2 + 32 * 64 * 8 * 2 + 128 * 4;       // 67072 B
    const int smem9  = (64 * 18 * 2 + 9 * 64 * 2 + 128) * (int)sizeof(float);  // 14336 B
    cudaFuncSetAttribute((const void*)node_update64,
                         cudaFuncAttributeMaxDynamicSharedMemorySize, smem64);

    const int NB = (NN + 63) / 64;

    // ---- slotted CSR build + prep (fused) ----
    cudaMemsetAsync(pCnt, 0, NN * sizeof(int));
    place_prep<<<(EE + 511) / 512, 512>>>(src, dst, ew, pCnt, pEpack, x, pX, batch, pGoff);

    // ---- layer 0 ----
    agg_csr4<<<(NN + 63) / 64, 256>>>(pX, pCnt, pEpack, pA, pStats);
    node_update9<<<NB, 128, smem9>>>(pA, pX, Wrel0, Wroot0, b0, pB, pStats);
    bn_act_h<<<(NN * 8 + 255) / 256, 256>>>(pB, pStats, g0, be0, pH);

    // ---- layer 1 ----
    agg_csr_h<<<(NN + 31) / 32, 256>>>(pH, pCnt, pEpack, pA);
    node_update64<<<NB, 128, smem64>>>(pA, pH, Wrel1, Wroot1, b1, (__half*)pB, pStats + 128);
    bn_act_h<<<(NN * 8 + 255) / 256, 256>>>(pB, pStats + 128, g1, be1, pH);

    // ---- layer 2 ----
    agg_csr_h<<<(NN + 31) / 32, 256>>>(pH, pCnt, pEpack, pA);
    pool2_head<<<GG, 64>>>(pA, pH, Wrel2, Wroot2, b2, pGoff, Wl1, bl1, Wl2, bl2, out);
}

// round 13
// speedup vs baseline: 1.0902x; 1.0209x over previous
#include <cuda_runtime.h>
#include <cuda_fp16.h>

#define NN 100000
#define EE 1600000
#define GG 1024
#define CAP 64

typedef unsigned long long ull;

// -------------------- device scratch --------------------
__device__ uint4 g_Ah[(size_t)NN * 8];       // aggregation output (fp16: 64 halves/node)
__device__ float g_A4[(size_t)NN * 16];      // layer-0 aggregation (fp32, 16-wide)
__device__ uint4 g_B[(size_t)NN * 8];        // raw layer outputs (fp16)
__device__ uint4 g_H[(size_t)NN * 8];        // activated features fp16
__device__ float g_xpad[(size_t)NN * 16];
__device__ int   g_cnt[NN];
__device__ int2  g_epack[(size_t)NN * CAP + 128];
__device__ int   g_goff[GG + 1];
__device__ float g_stats[256];

__device__ __forceinline__ void fma2(ull& d, ull a, ull b) {
    asm("fma.rn.f32x2 %0, %1, %2, %0;" : "+l"(d) : "l"(a), "l"(b));
}
__device__ __forceinline__ float2 unpack2(ull v) {
    float2 r; asm("mov.b64 {%0,%1}, %2;" : "=f"(r.x), "=f"(r.y) : "l"(v)); return r;
}
__device__ __forceinline__ ull pack2(float lo, float hi) {
    ull r; asm("mov.b64 %0, {%1,%2};" : "=l"(r) : "f"(lo), "f"(hi)); return r;
}
__device__ __forceinline__ ull rep2(float v) {
    ull r; asm("mov.b64 %0, {%1,%1};" : "=l"(r) : "f"(v)); return r;
}

// -------------------- fused placement + xpad + graph bounds ---------------------
__global__ void place_prep(const int* __restrict__ src, const int* __restrict__ dst,
                           const float* __restrict__ ew, int* __restrict__ cnt,
                           int2* __restrict__ epack,
                           const float* __restrict__ x, float* __restrict__ xp,
                           const int* __restrict__ batch, int* __restrict__ goff) {
    int e = blockIdx.x * blockDim.x + threadIdx.x;
    if (e < EE) {
        int d = dst[e];
        int p = atomicAdd(&cnt[d], 1);
        epack[((size_t)d << 6) + p] = make_int2(src[e], __float_as_int(ew[e]));
    }
    if (e < NN * 16) { int n = e >> 4, c = e & 15; xp[e] = (c < 9) ? x[n * 9 + c] : 0.f; }
    if (e < NN) {
        int bi = batch[e];
        if (e == 0) { for (int g = 0; g <= bi; g++) goff[g] = 0; }
        else { int bp = batch[e - 1]; for (int g = bp + 1; g <= bi; g++) goff[g] = e; }
        if (e == NN - 1) { for (int g = bi + 1; g <= GG; g++) goff[g] = NN; }
    }
}

// -------------------- layer-0 aggregation (fp32, unroll-4) ----------------------
__global__ void __launch_bounds__(256) agg_csr4(
    const float* __restrict__ h, const int* __restrict__ cnt,
    const int2* __restrict__ epack, float* __restrict__ agg, float* __restrict__ stats) {
    if (blockIdx.x == 0) stats[threadIdx.x] = 0.f;
    int node = blockIdx.x * 64 + (threadIdx.x >> 2);
    int lane = threadIdx.x & 3;
    if (node >= NN) return;
    int beg = node << 6, end = beg + cnt[node];
    float4 acc = make_float4(0.f, 0.f, 0.f, 0.f);
    int i = beg;
    for (; i + 3 < end; i += 4) {
        int2 e0 = epack[i], e1 = epack[i + 1], e2 = epack[i + 2], e3 = epack[i + 3];
        float4 v0 = ((const float4*)h)[(size_t)e0.x * 4 + lane];
        float4 v1 = ((const float4*)h)[(size_t)e1.x * 4 + lane];
        float4 v2 = ((const float4*)h)[(size_t)e2.x * 4 + lane];
        float4 v3 = ((const float4*)h)[(size_t)e3.x * 4 + lane];
        float w0 = __int_as_float(e0.y), w1 = __int_as_float(e1.y);
        float w2 = __int_as_float(e2.y), w3 = __int_as_float(e3.y);
        acc.x = fmaf(v0.x, w0, acc.x); acc.y = fmaf(v0.y, w0, acc.y);
        acc.z = fmaf(v0.z, w0, acc.z); acc.w = fmaf(v0.w, w0, acc.w);
        acc.x = fmaf(v1.x, w1, acc.x); acc.y = fmaf(v1.y, w1, acc.y);
        acc.z = fmaf(v1.z, w1, acc.z); acc.w = fmaf(v1.w, w1, acc.w);
        acc.x = fmaf(v2.x, w2, acc.x); acc.y = fmaf(v2.y, w2, acc.y);
        acc.z = fmaf(v2.z, w2, acc.z); acc.w = fmaf(v2.w, w2, acc.w);
        acc.x = fmaf(v3.x, w3, acc.x); acc.y = fmaf(v3.y, w3, acc.y);
        acc.z = fmaf(v3.z, w3, acc.z); acc.w = fmaf(v3.w, w3, acc.w);
    }
    for (; i < end; ++i) {
        int2 ep = epack[i];
        float w = __int_as_float(ep.y);
        float4 v = ((const float4*)h)[(size_t)ep.x * 4 + lane];
        acc.x = fmaf(v.x, w, acc.x); acc.y = fmaf(v.y, w, acc.y);
        acc.z = fmaf(v.z, w, acc.z); acc.w = fmaf(v.w, w, acc.w);
    }
    ((float4*)agg)[(size_t)node * 4 + lane] = acc;
}

// -------------------- fp16 aggregation (unroll-4, fp16 out) --------------------
__device__ __forceinline__ void accum8(float* acc, uint4 r, float w) {
    __half2* hp = (__half2*)&r;
#pragma unroll
    for (int j = 0; j < 4; j++) {
        float2 f = __half22float2(hp[j]);
        acc[2 * j]     = fmaf(f.x, w, acc[2 * j]);
        acc[2 * j + 1] = fmaf(f.y, w, acc[2 * j + 1]);
    }
}

__global__ void __launch_bounds__(256) agg_csr_h(
    const uint4* __restrict__ h, const int* __restrict__ cnt,
    const int2* __restrict__ epack, uint4* __restrict__ aggh) {
    int node = blockIdx.x * 32 + (threadIdx.x >> 3);
    int lane = threadIdx.x & 7;
    if (node >= NN) return;
    int beg = node << 6, end = beg + cnt[node];
    float acc[8];
#pragma unroll
    for (int j = 0; j < 8; j++) acc[j] = 0.f;
    int i = beg;
    for (; i + 3 < end; i += 4) {
        int2 e0 = epack[i], e1 = epack[i + 1], e2 = epack[i + 2], e3 = epack[i + 3];
        uint4 r0 = h[(size_t)e0.x * 8 + lane];
        uint4 r1 = h[(size_t)e1.x * 8 + lane];
        uint4 r2 = h[(size_t)e2.x * 8 + lane];
        uint4 r3 = h[(size_t)e3.x * 8 + lane];
        accum8(acc, r0, __int_as_float(e0.y));
        accum8(acc, r1, __int_as_float(e1.y));
        accum8(acc, r2, __int_as_float(e2.y));
        accum8(acc, r3, __int_as_float(e3.y));
    }
    for (; i < end; ++i) {
        int2 e0 = epack[i];
        uint4 r0 = h[(size_t)e0.x * 8 + lane];
        accum8(acc, r0, __int_as_float(e0.y));
    }
    __half2 o0 = __floats2half2_rn(acc[0], acc[1]);
    __half2 o1 = __floats2half2_rn(acc[2], acc[3]);
    __half2 o2 = __floats2half2_rn(acc[4], acc[5]);
    __half2 o3 = __floats2half2_rn(acc[6], acc[7]);
    uint4 o;
    o.x = *(unsigned*)&o0; o.y = *(unsigned*)&o1;
    o.z = *(unsigned*)&o2; o.w = *(unsigned*)&o3;
    aggh[(size_t)node * 8 + lane] = o;
}

// -------------------- layer-0 node update (K=9, f32x2 feature pairs, fp16 out) --
__global__ void __launch_bounds__(128) node_update9(
    const float* __restrict__ Ag, const float* __restrict__ Xin,
    const float* __restrict__ Wrel, const float* __restrict__ Wroot,
    const float* __restrict__ bias, uint4* __restrict__ Outh, float* stats) {
    constexpr int K = 9, PAD = 18;
    extern __shared__ float sm[];
    float* sA   = sm;
    float* sX   = sA + 64 * PAD;
    float* sWr  = sX + 64 * PAD;
    float* sWo  = sWr + K * 64;
    float* sSum = sWo + K * 64;
    float* sSq  = sSum + 64;

    const int tid = threadIdx.x;
    const int base = blockIdx.x * 64;

    for (int i = tid; i < K * 16; i += 128) {
        ((float4*)sWr)[i] = ((const float4*)Wrel)[i];
        ((float4*)sWo)[i] = ((const float4*)Wroot)[i];
    }
    for (int i = tid; i < 64 * 4; i += 128) {
        int r = i >> 2, c = i & 3;
        int n = base + r;
        float4 va = make_float4(0.f, 0.f, 0.f, 0.f), vx = va;
        if (n < NN) {
            va = *(const float4*)&Ag[(size_t)n * 16 + c * 4];
            vx = *(const float4*)&Xin[(size_t)n * 16 + c * 4];
        }
        ull* pa = (ull*)&sA[r * PAD + c * 4];
        ull* px = (ull*)&sX[r * PAD + c * 4];
        pa[0] = pack2(va.x, va.y); pa[1] = pack2(va.z, va.w);
        px[0] = pack2(vx.x, vx.y); px[1] = pack2(vx.z, vx.w);
    }
    if (tid < 64) { sSum[tid] = 0.f; sSq[tid] = 0.f; }
    __syncthreads();

    const int f0 = (tid & 7) * 8;
    const int ng = (tid >> 3) * 4;

    ull acc2[4][4];
#pragma unroll
    for (int i = 0; i < 4; i++)
#pragma unroll
        for (int p = 0; p < 4; p++) acc2[i][p] = 0ull;

#pragma unroll
    for (int k = 0; k < K; ++k) {
        ull ra[4], rx[4];
#pragma unroll
        for (int i = 0; i < 4; i++) {
            ra[i] = rep2(sA[(ng + i) * PAD + k]);
            rx[i] = rep2(sX[(ng + i) * PAD + k]);
        }
        ulonglong2 wr0 = *(const ulonglong2*)&sWr[k * 64 + f0];
        ulonglong2 wr1 = *(const ulonglong2*)&sWr[k * 64 + f0 + 4];
        ulonglong2 wo0 = *(const ulonglong2*)&sWo[k * 64 + f0];
        ulonglong2 wo1 = *(const ulonglong2*)&sWo[k * 64 + f0 + 4];
#pragma unroll
        for (int i = 0; i < 4; i++) {
            fma2(acc2[i][0], ra[i], wr0.x);
            fma2(acc2[i][1], ra[i], wr0.y);
            fma2(acc2[i][2], ra[i], wr1.x);
            fma2(acc2[i][3], ra[i], wr1.y);
            fma2(acc2[i][0], rx[i], wo0.x);
            fma2(acc2[i][1], rx[i], wo0.y);
            fma2(acc2[i][2], rx[i], wo1.x);
            fma2(acc2[i][3], rx[i], wo1.y);
        }
    }

    float bz[8];
    *(float4*)&bz[0] = *(const float4*)&bias[f0];
    *(float4*)&bz[4] = *(const float4*)&bias[f0 + 4];

    float s[8], q[8];
#pragma unroll
    for (int j = 0; j < 8; j++) { s[j] = 0.f; q[j] = 0.f; }

#pragma unroll
    for (int i = 0; i < 4; i++) {
        int n = base + ng + i;
        if (n < NN) {
            float o[8];
#pragma unroll
            for (int p = 0; p < 4; p++) {
                float2 v = unpack2(acc2[i][p]);
                o[2 * p]     = v.x + bz[2 * p];
                o[2 * p + 1] = v.y + bz[2 * p + 1];
            }
            __half2 h0 = __floats2half2_rn(o[0], o[1]);
            __half2 h1 = __floats2half2_rn(o[2], o[3]);
            __half2 h2 = __floats2half2_rn(o[4], o[5]);
            __half2 h3 = __floats2half2_rn(o[6], o[7]);
            uint4 ov;
            ov.x = *(unsigned*)&h0; ov.y = *(unsigned*)&h1;
            ov.z = *(unsigned*)&h2; ov.w = *(unsigned*)&h3;
            Outh[(size_t)n * 8 + (tid & 7)] = ov;
#pragma unroll
            for (int j = 0; j < 8; j++) { s[j] += o[j]; q[j] += o[j] * o[j]; }
        }
    }
#pragma unroll
    for (int j = 0; j < 8; j++) {
        atomicAdd(&sSum[f0 + j], s[j]);
        atomicAdd(&sSq[f0 + j], q[j]);
    }
    __syncthreads();
    if (tid < 64) {
        atomicAdd(&stats[tid], sSum[tid]);
        atomicAdd(&stats[64 + tid], sSq[tid]);
    }
}

// -------------------- f32x2 node update (K=64), fp16 Ag + Xin, fp16 out ---------
__global__ void __launch_bounds__(128) node_update64(
    const uint4* __restrict__ Agh, const uint4* __restrict__ Xh,
    const float* __restrict__ Wrel, const float* __restrict__ Wroot,
    const float* __restrict__ bias, __half* __restrict__ Outh, float* stats) {
    constexpr int PAD = 66;
    extern __shared__ float sm[];
    float* sA   = sm;
    float* sX   = sA + 64 * PAD;
    ull*   sWr  = (ull*)(sX + 64 * PAD);
    ull*   sWo  = sWr + 32 * 64;
    float* sSum = (float*)(sWo + 32 * 64);
    float* sSq  = sSum + 64;

    const int tid = threadIdx.x;
    const int base = blockIdx.x * 64;

    for (int idx = tid; idx < 32 * 16; idx += 128) {
        int k2 = idx >> 4, c4 = idx & 15;
        float4 r0 = ((const float4*)Wrel)[(2 * k2) * 16 + c4];
        float4 r1 = ((const float4*)Wrel)[(2 * k2 + 1) * 16 + c4];
        ull* p = &sWr[k2 * 64 + c4 * 4];
        p[0] = pack2(r0.x, r1.x); p[1] = pack2(r0.y, r1.y);
        p[2] = pack2(r0.z, r1.z); p[3] = pack2(r0.w, r1.w);
        r0 = ((const float4*)Wroot)[(2 * k2) * 16 + c4];
        r1 = ((const float4*)Wroot)[(2 * k2 + 1) * 16 + c4];
        p = &sWo[k2 * 64 + c4 * 4];
        p[0] = pack2(r0.x, r1.x); p[1] = pack2(r0.y, r1.y);
        p[2] = pack2(r0.z, r1.z); p[3] = pack2(r0.w, r1.w);
    }
    for (int i = tid; i < 64 * 8; i += 128) {
        int r = i >> 3, c = i & 7;
        int n = base + r;
        uint4 va = make_uint4(0u, 0u, 0u, 0u), vx = va;
        if (n < NN) {
            va = Agh[(size_t)n * 8 + c];
            vx = Xh[(size_t)n * 8 + c];
        }
        __half2* hpa = (__half2*)&va;
        __half2* hpx = (__half2*)&vx;
        float* oa = &sA[r * PAD + c * 8];
        float* ox = &sX[r * PAD + c * 8];
#pragma unroll
        for (int j = 0; j < 4; j++) {
            float2 fa = __half22float2(hpa[j]);
            float2 fx = __half22float2(hpx[j]);
            oa[2 * j] = fa.x; oa[2 * j + 1] = fa.y;
            ox[2 * j] = fx.x; ox[2 * j + 1] = fx.y;
        }
    }
    if (tid < 64) { sSum[tid] = 0.f; sSq[tid] = 0.f; }
    __syncthreads();

    const int f0 = (tid & 7) * 2;
    const int ng = (tid >> 3) * 4;

    ull acc2[4][8];
#pragma unroll
    for (int i = 0; i < 4; i++)
#pragma unroll
        for (int j = 0; j < 8; j++) acc2[i][j] = 0ull;

#pragma unroll 2
    for (int k2 = 0; k2 < 32; ++k2) {
        ull av[4], xv[4];
#pragma unroll
        for (int i = 0; i < 4; i++) {
            av[i] = *(const ull*)&sA[(ng + i) * PAD + 2 * k2];
            xv[i] = *(const ull*)&sX[(ng + i) * PAD + 2 * k2];
        }
#pragma unroll
        for (int c = 0; c < 4; c++) {
            ulonglong2 wr = *(const ulonglong2*)&sWr[k2 * 64 + f0 + 16 * c];
            ulonglong2 wo = *(const ulonglong2*)&sWo[k2 * 64 + f0 + 16 * c];
#pragma unroll
            for (int i = 0; i < 4; i++) {
                fma2(acc2[i][2 * c],     av[i], wr.x);
                fma2(acc2[i][2 * c + 1], av[i], wr.y);
                fma2(acc2[i][2 * c],     xv[i], wo.x);
                fma2(acc2[i][2 * c + 1], xv[i], wo.y);
            }
        }
    }

    float bz[8];
#pragma unroll
    for (int c = 0; c < 4; c++) {
        float2 b2 = *(const float2*)&bias[f0 + 16 * c];
        bz[2 * c] = b2.x; bz[2 * c + 1] = b2.y;
    }

    float s[8], q[8];
#pragma unroll
    for (int j = 0; j < 8; j++) { s[j] = 0.f; q[j] = 0.f; }

#pragma unroll
    for (int i = 0; i < 4; i++) {
        int n = base + ng + i;
        if (n < NN) {
#pragma unroll
            for (int c = 0; c < 4; c++) {
                float2 e0 = unpack2(acc2[i][2 * c]);
                float2 e1 = unpack2(acc2[i][2 * c + 1]);
                float o0 = e0.x + e0.y + bz[2 * c];
                float o1 = e1.x + e1.y + bz[2 * c + 1];
                __half2 hv = __floats2half2_rn(o0, o1);
                *(__half2*)&Outh[(size_t)n * 64 + f0 + 16 * c] = hv;
                s[2 * c] += o0; q[2 * c] += o0 * o0;
                s[2 * c + 1] += o1; q[2 * c + 1] += o1 * o1;
            }
        }
    }
#pragma unroll
    for (int c = 0; c < 4; c++) {
        atomicAdd(&sSum[f0 + 16 * c],     s[2 * c]);
        atomicAdd(&sSum[f0 + 16 * c + 1], s[2 * c + 1]);
        atomicAdd(&sSq[f0 + 16 * c],      q[2 * c]);
        atomicAdd(&sSq[f0 + 16 * c + 1],  q[2 * c + 1]);
    }
    __syncthreads();
    if (tid < 64) {
        atomicAdd(&stats[tid], sSum[tid]);
        atomicAdd(&stats[64 + tid], sSq[tid]);
    }
}

// -------------------- BN finalize + apply + ReLU (fp16 in/out, 2 uint4/thread) --
__global__ void __launch_bounds__(256) bn_act_h(
    const uint4* __restrict__ inh, const float* __restrict__ stats,
    const float* __restrict__ g, const float* __restrict__ be,
    uint4* __restrict__ outh) {
    __shared__ float sc[64], sh[64];
    if (threadIdx.x < 64) {
        int f = threadIdx.x;
        const float inv = 1.f / (float)NN;
        float m = stats[f] * inv;
        float var = stats[64 + f] * inv - m * m;
        float s = g[f] * rsqrtf(var + 1e-5f);
        sc[f] = s;
        sh[f] = fmaf(-m, s, be[f]);
    }
    __syncthreads();
    int t = blockIdx.x * blockDim.x + threadIdx.x;
#pragma unroll
    for (int u = 0; u < 2; u++) {
        int i = t * 2 + u;
        if (i >= NN * 8) return;
        int c8 = (i & 7) * 8;
        uint4 v = inh[i];
        __half2* hp = (__half2*)&v;
        float o[8];
#pragma unroll
        for (int j = 0; j < 4; j++) {
            float2 f = __half22float2(hp[j]);
            o[2 * j]     = fmaxf(fmaf(f.x, sc[c8 + 2 * j],     sh[c8 + 2 * j]), 0.f);
            o[2 * j + 1] = fmaxf(fmaf(f.y, sc[c8 + 2 * j + 1], sh[c8 + 2 * j + 1]), 0.f);
        }
        __half2 h0 = __floats2half2_rn(o[0], o[1]);
        __half2 h1 = __floats2half2_rn(o[2], o[3]);
        __half2 h2 = __floats2half2_rn(o[4], o[5]);
        __half2 h3 = __floats2half2_rn(o[6], o[7]);
        uint4 ov;
        ov.x = *(unsigned*)&h0; ov.y = *(unsigned*)&h1;
        ov.z = *(unsigned*)&h2; ov.w = *(unsigned*)&h3;
        outh[i] = ov;
    }
}

// -------------------- layer-2 pooled GEMM + MLP head (fp16 agg) -----------------
__global__ void pool2_head(const uint4* __restrict__ Agh, const uint4* __restrict__ Xh,
                           const float* __restrict__ W2rel, const float* __restrict__ W2root,
                           const float* __restrict__ b2, const int* __restrict__ goff,
                           const float* __restrict__ Wl1, const float* __restrict__ bl1,
                           const float* __restrict__ Wl2, const float* __restrict__ bl2,
                           float* __restrict__ out) {
    __shared__ float sAg[64], sXp[64], sPool[64], sz[64];
    int g = blockIdx.x, t = threadIdx.x;
    int beg = goff[g], end = goff[g + 1];
    const __half* ah = (const __half*)Agh;
    const __half* xh = (const __half*)Xh;
    float sa = 0.f, sx = 0.f;
    for (int n = beg; n < end; ++n) {
        sa += __half2float(ah[(size_t)n * 64 + t]);
        sx += __half2float(xh[(size_t)n * 64 + t]);
    }
    sAg[t] = sa; sXp[t] = sx;
    __syncthreads();
    float cnt = (float)(end - beg);
    float acc = cnt * b2[t];
#pragma unroll 8
    for (int k = 0; k < 64; k++)
        acc += sAg[k] * W2rel[k * 64 + t] + sXp[k] * W2root[k * 64 + t];
    sPool[t] = acc / fmaxf(cnt, 1.f);
    __syncthreads();
    float z = bl1[t];
#pragma unroll 8
    for (int k = 0; k < 64; k++) z = fmaf(sPool[k], Wl1[k * 64 + t], z);
    sz[t] = fmaxf(z, 0.f);
    __syncthreads();
    if (t < 6) {
        float o = bl2[t];
#pragma unroll 8
        for (int k = 0; k < 64; k++) o = fmaf(sz[k], Wl2[k * 6 + t], o);
        out[g * 6 + t] = o;
    }
}

// -------------------- launch --------------------
extern "C" void kernel_launch(void* const* d_in, const int* in_sizes, int n_in,
                              void* d_out, int out_size) {
    const float* x     = (const float*)d_in[0];
    const int*   ei    = (const int*)d_in[1];
    const float* ew    = (const float*)d_in[2];
    const int*   batch = (const int*)d_in[3];
    const float *Wrel0 = (const float*)d_in[4],  *Wroot0 = (const float*)d_in[5],  *b0 = (const float*)d_in[6];
    const float *Wrel1 = (const float*)d_in[7],  *Wroot1 = (const float*)d_in[8],  *b1 = (const float*)d_in[9];
    const float *Wrel2 = (const float*)d_in[10], *Wroot2 = (const float*)d_in[11], *b2 = (const float*)d_in[12];
    const float *g0 = (const float*)d_in[13], *be0 = (const float*)d_in[14];
    const float *g1 = (const float*)d_in[15], *be1 = (const float*)d_in[16];
    const float *Wl1 = (const float*)d_in[17], *bl1 = (const float*)d_in[18];
    const float *Wl2 = (const float*)d_in[19], *bl2 = (const float*)d_in[20];
    float* out = (float*)d_out;

    const int* src = ei;
    const int* dst = ei + EE;

    float *pA4, *pX, *pStats;
    uint4 *pAh, *pB, *pH;
    int *pCnt, *pGoff;
    int2* pEpack;
    cudaGetSymbolAddress((void**)&pAh, g_Ah);
    cudaGetSymbolAddress((void**)&pA4, g_A4);
    cudaGetSymbolAddress((void**)&pB, g_B);
    cudaGetSymbolAddress((void**)&pH, g_H);
    cudaGetSymbolAddress((void**)&pX, g_xpad);
    cudaGetSymbolAddress((void**)&pStats, g_stats);
    cudaGetSymbolAddress((void**)&pCnt, g_cnt);
    cudaGetSymbolAddress((void**)&pGoff, g_goff);
    cudaGetSymbolAddress((void**)&pEpack, g_epack);

    const int smem64 = 64 * 66 * 4 * 2 + 32 * 64 * 8 * 2 + 128 * 4;       // 67072 B
    const int smem9  = (64 * 18 * 2 + 9 * 64 * 2 + 128) * (int)sizeof(float);  // 14336 B
    cudaFuncSetAttribute((const void*)node_update64,
                         cudaFuncAttributeMaxDynamicSharedMemorySize, smem64);

    const int NB = (NN + 63) / 64;

    // ---- slotted CSR build + prep (fused) ----
    cudaMemsetAsync(pCnt, 0, NN * sizeof(int));
    place_prep<<<(EE + 511) / 512, 512>>>(src, dst, ew, pCnt, pEpack, x, pX, batch, pGoff);

    // ---- layer 0 ----
    agg_csr4<<<(NN + 63) / 64, 256>>>(pX, pCnt, pEpack, pA4, pStats);
    node_update9<<<NB, 128, smem9>>>(pA4, pX, Wrel0, Wroot0, b0, pB, pStats);
    bn_act_h<<<(NN * 4 + 255) / 256, 256>>>(pB, pStats, g0, be0, pH);

    // ---- layer 1 ----
    agg_csr_h<<<(NN + 31) / 32, 256>>>(pH, pCnt, pEpack, pAh);
    node_update64<<<NB, 128, smem64>>>(pAh, pH, Wrel1, Wroot1, b1, (__half*)pB, pStats + 128);
    bn_act_h<<<(NN * 4 + 255) / 256, 256>>>(pB, pStats + 128, g1, be1, pH);

    // ---- layer 2 ----
    agg_csr_h<<<(NN + 31) / 32, 256>>>(pH, pCnt, pEpack, pAh);
    pool2_head<<<GG, 64>>>(pAh, pH, Wrel2, Wroot2, b2, pGoff, Wl1, bl1, Wl2, bl2, out);
}

// round 14
// speedup vs baseline: 1.1165x; 1.0241x over previous
#include <cuda_runtime.h>
#include <cuda_fp16.h>

#define NN 100000
#define EE 1600000
#define GG 1024
#define CAP 64

typedef unsigned long long ull;

// -------------------- device scratch --------------------
__device__ uint4 g_Ah[(size_t)NN * 8];       // aggregation output (fp16: 64 halves/node)
__device__ float g_A4[(size_t)NN * 16];      // layer-0 aggregation (fp32, 16-wide)
__device__ uint4 g_B[(size_t)NN * 8];        // raw layer outputs (fp16)
__device__ uint4 g_H[(size_t)NN * 8];        // activated features fp16
__device__ float g_xpad[(size_t)NN * 16];
__device__ int   g_cnt[NN];
__device__ int2  g_epack[(size_t)NN * CAP + 128];
__device__ int   g_goff[GG + 1];
__device__ float g_stats[256];

__device__ __forceinline__ void fma2(ull& d, ull a, ull b) {
    asm("fma.rn.f32x2 %0, %1, %2, %0;" : "+l"(d) : "l"(a), "l"(b));
}
__device__ __forceinline__ float2 unpack2(ull v) {
    float2 r; asm("mov.b64 {%0,%1}, %2;" : "=f"(r.x), "=f"(r.y) : "l"(v)); return r;
}
__device__ __forceinline__ ull pack2(float lo, float hi) {
    ull r; asm("mov.b64 %0, {%1,%2};" : "=l"(r) : "f"(lo), "f"(hi)); return r;
}
__device__ __forceinline__ ull rep2(float v) {
    ull r; asm("mov.b64 %0, {%1,%1};" : "=l"(r) : "f"(v)); return r;
}

// -------------------- fused placement + xpad + graph bounds ---------------------
__global__ void place_prep(const int* __restrict__ src, const int* __restrict__ dst,
                           const float* __restrict__ ew, int* __restrict__ cnt,
                           int2* __restrict__ epack,
                           const float* __restrict__ x, float* __restrict__ xp,
                           const int* __restrict__ batch, int* __restrict__ goff) {
    int e = blockIdx.x * blockDim.x + threadIdx.x;
    if (e < EE) {
        int d = dst[e];
        int p = atomicAdd(&cnt[d], 1);
        epack[((size_t)d << 6) + p] = make_int2(src[e], __float_as_int(ew[e]));
    }
    if (e < NN * 16) { int n = e >> 4, c = e & 15; xp[e] = (c < 9) ? x[n * 9 + c] : 0.f; }
    if (e < NN) {
        int bi = batch[e];
        if (e == 0) { for (int g = 0; g <= bi; g++) goff[g] = 0; }
        else { int bp = batch[e - 1]; for (int g = bp + 1; g <= bi; g++) goff[g] = e; }
        if (e == NN - 1) { for (int g = bi + 1; g <= GG; g++) goff[g] = NN; }
    }
}

// -------------------- layer-0 aggregation (fp32, unroll-4, int4 epack) ----------
__global__ void __launch_bounds__(256) agg_csr4(
    const float* __restrict__ h, const int* __restrict__ cnt,
    const int2* __restrict__ epack, float* __restrict__ agg, float* __restrict__ stats) {
    if (blockIdx.x == 0) stats[threadIdx.x] = 0.f;
    int node = blockIdx.x * 64 + (threadIdx.x >> 2);
    int lane = threadIdx.x & 3;
    if (node >= NN) return;
    int beg = node << 6, end = beg + cnt[node];
    float4 acc = make_float4(0.f, 0.f, 0.f, 0.f);
    int i = beg;
    for (; i + 3 < end; i += 4) {
        int4 p01 = *(const int4*)&epack[i];       // (s0,w0,s1,w1)
        int4 p23 = *(const int4*)&epack[i + 2];   // (s2,w2,s3,w3)
        float4 v0 = ((const float4*)h)[(size_t)p01.x * 4 + lane];
        float4 v1 = ((const float4*)h)[(size_t)p01.z * 4 + lane];
        float4 v2 = ((const float4*)h)[(size_t)p23.x * 4 + lane];
        float4 v3 = ((const float4*)h)[(size_t)p23.z * 4 + lane];
        float w0 = __int_as_float(p01.y), w1 = __int_as_float(p01.w);
        float w2 = __int_as_float(p23.y), w3 = __int_as_float(p23.w);
        acc.x = fmaf(v0.x, w0, acc.x); acc.y = fmaf(v0.y, w0, acc.y);
        acc.z = fmaf(v0.z, w0, acc.z); acc.w = fmaf(v0.w, w0, acc.w);
        acc.x = fmaf(v1.x, w1, acc.x); acc.y = fmaf(v1.y, w1, acc.y);
        acc.z = fmaf(v1.z, w1, acc.z); acc.w = fmaf(v1.w, w1, acc.w);
        acc.x = fmaf(v2.x, w2, acc.x); acc.y = fmaf(v2.y, w2, acc.y);
        acc.z = fmaf(v2.z, w2, acc.z); acc.w = fmaf(v2.w, w2, acc.w);
        acc.x = fmaf(v3.x, w3, acc.x); acc.y = fmaf(v3.y, w3, acc.y);
        acc.z = fmaf(v3.z, w3, acc.z); acc.w = fmaf(v3.w, w3, acc.w);
    }
    for (; i < end; ++i) {
        int2 ep = epack[i];
        float w = __int_as_float(ep.y);
        float4 v = ((const float4*)h)[(size_t)ep.x * 4 + lane];
        acc.x = fmaf(v.x, w, acc.x); acc.y = fmaf(v.y, w, acc.y);
        acc.z = fmaf(v.z, w, acc.z); acc.w = fmaf(v.w, w, acc.w);
    }
    ((float4*)agg)[(size_t)node * 4 + lane] = acc;
}

// -------------------- fp16 aggregation (unroll-4, int4 epack, fp16 out) ---------
__device__ __forceinline__ void accum8(float* acc, uint4 r, float w) {
    __half2* hp = (__half2*)&r;
#pragma unroll
    for (int j = 0; j < 4; j++) {
        float2 f = __half22float2(hp[j]);
        acc[2 * j]     = fmaf(f.x, w, acc[2 * j]);
        acc[2 * j + 1] = fmaf(f.y, w, acc[2 * j + 1]);
    }
}

__global__ void __launch_bounds__(256) agg_csr_h(
    const uint4* __restrict__ h, const int* __restrict__ cnt,
    const int2* __restrict__ epack, uint4* __restrict__ aggh) {
    int node = blockIdx.x * 32 + (threadIdx.x >> 3);
    int lane = threadIdx.x & 7;
    if (node >= NN) return;
    int beg = node << 6, end = beg + cnt[node];
    float acc[8];
#pragma unroll
    for (int j = 0; j < 8; j++) acc[j] = 0.f;
    int i = beg;
    for (; i + 3 < end; i += 4) {
        int4 p01 = *(const int4*)&epack[i];       // (s0,w0,s1,w1)
        int4 p23 = *(const int4*)&epack[i + 2];   // (s2,w2,s3,w3)
        uint4 r0 = h[(size_t)p01.x * 8 + lane];
        uint4 r1 = h[(size_t)p01.z * 8 + lane];
        uint4 r2 = h[(size_t)p23.x * 8 + lane];
        uint4 r3 = h[(size_t)p23.z * 8 + lane];
        accum8(acc, r0, __int_as_float(p01.y));
        accum8(acc, r1, __int_as_float(p01.w));
        accum8(acc, r2, __int_as_float(p23.y));
        accum8(acc, r3, __int_as_float(p23.w));
    }
    for (; i < end; ++i) {
        int2 e0 = epack[i];
        uint4 r0 = h[(size_t)e0.x * 8 + lane];
        accum8(acc, r0, __int_as_float(e0.y));
    }
    __half2 o0 = __floats2half2_rn(acc[0], acc[1]);
    __half2 o1 = __floats2half2_rn(acc[2], acc[3]);
    __half2 o2 = __floats2half2_rn(acc[4], acc[5]);
    __half2 o3 = __floats2half2_rn(acc[6], acc[7]);
    uint4 o;
    o.x = *(unsigned*)&o0; o.y = *(unsigned*)&o1;
    o.z = *(unsigned*)&o2; o.w = *(unsigned*)&o3;
    aggh[(size_t)node * 8 + lane] = o;
}

// -------------------- layer-0 node update (K=9, f32x2 feature pairs, fp16 out) --
__global__ void __launch_bounds__(128) node_update9(
    const float* __restrict__ Ag, const float* __restrict__ Xin,
    const float* __restrict__ Wrel, const float* __restrict__ Wroot,
    const float* __restrict__ bias, uint4* __restrict__ Outh, float* stats) {
    constexpr int K = 9, PAD = 18;
    extern __shared__ float sm[];
    float* sA   = sm;
    float* sX   = sA + 64 * PAD;
    float* sWr  = sX + 64 * PAD;
    float* sWo  = sWr + K * 64;
    float* sSum = sWo + K * 64;
    float* sSq  = sSum + 64;

    const int tid = threadIdx.x;
    const int base = blockIdx.x * 64;

    for (int i = tid; i < K * 16; i += 128) {
        ((float4*)sWr)[i] = ((const float4*)Wrel)[i];
        ((float4*)sWo)[i] = ((const float4*)Wroot)[i];
    }
    for (int i = tid; i < 64 * 4; i += 128) {
        int r = i >> 2, c = i & 3;
        int n = base + r;
        float4 va = make_float4(0.f, 0.f, 0.f, 0.f), vx = va;
        if (n < NN) {
            va = *(const float4*)&Ag[(size_t)n * 16 + c * 4];
            vx = *(const float4*)&Xin[(size_t)n * 16 + c * 4];
        }
        ull* pa = (ull*)&sA[r * PAD + c * 4];
        ull* px = (ull*)&sX[r * PAD + c * 4];
        pa[0] = pack2(va.x, va.y); pa[1] = pack2(va.z, va.w);
        px[0] = pack2(vx.x, vx.y); px[1] = pack2(vx.z, vx.w);
    }
    if (tid < 64) { sSum[tid] = 0.f; sSq[tid] = 0.f; }
    __syncthreads();

    const int f0 = (tid & 7) * 8;
    const int ng = (tid >> 3) * 4;

    ull acc2[4][4];
#pragma unroll
    for (int i = 0; i < 4; i++)
#pragma unroll
        for (int p = 0; p < 4; p++) acc2[i][p] = 0ull;

#pragma unroll
    for (int k = 0; k < K; ++k) {
        ull ra[4], rx[4];
#pragma unroll
        for (int i = 0; i < 4; i++) {
            ra[i] = rep2(sA[(ng + i) * PAD + k]);
            rx[i] = rep2(sX[(ng + i) * PAD + k]);
        }
        ulonglong2 wr0 = *(const ulonglong2*)&sWr[k * 64 + f0];
        ulonglong2 wr1 = *(const ulonglong2*)&sWr[k * 64 + f0 + 4];
        ulonglong2 wo0 = *(const ulonglong2*)&sWo[k * 64 + f0];
        ulonglong2 wo1 = *(const ulonglong2*)&sWo[k * 64 + f0 + 4];
#pragma unroll
        for (int i = 0; i < 4; i++) {
            fma2(acc2[i][0], ra[i], wr0.x);
            fma2(acc2[i][1], ra[i], wr0.y);
            fma2(acc2[i][2], ra[i], wr1.x);
            fma2(acc2[i][3], ra[i], wr1.y);
            fma2(acc2[i][0], rx[i], wo0.x);
            fma2(acc2[i][1], rx[i], wo0.y);
            fma2(acc2[i][2], rx[i], wo1.x);
            fma2(acc2[i][3], rx[i], wo1.y);
        }
    }

    float bz[8];
    *(float4*)&bz[0] = *(const float4*)&bias[f0];
    *(float4*)&bz[4] = *(const float4*)&bias[f0 + 4];

    float s[8], q[8];
#pragma unroll
    for (int j = 0; j < 8; j++) { s[j] = 0.f; q[j] = 0.f; }

#pragma unroll
    for (int i = 0; i < 4; i++) {
        int n = base + ng + i;
        if (n < NN) {
            float o[8];
#pragma unroll
            for (int p = 0; p < 4; p++) {
                float2 v = unpack2(acc2[i][p]);
                o[2 * p]     = v.x + bz[2 * p];
                o[2 * p + 1] = v.y + bz[2 * p + 1];
            }
            __half2 h0 = __floats2half2_rn(o[0], o[1]);
            __half2 h1 = __floats2half2_rn(o[2], o[3]);
            __half2 h2 = __floats2half2_rn(o[4], o[5]);
            __half2 h3 = __floats2half2_rn(o[6], o[7]);
            uint4 ov;
            ov.x = *(unsigned*)&h0; ov.y = *(unsigned*)&h1;
            ov.z = *(unsigned*)&h2; ov.w = *(unsigned*)&h3;
            Outh[(size_t)n * 8 + (tid & 7)] = ov;
#pragma unroll
            for (int j = 0; j < 8; j++) { s[j] += o[j]; q[j] += o[j] * o[j]; }
        }
    }
#pragma unroll
    for (int j = 0; j < 8; j++) {
        atomicAdd(&sSum[f0 + j], s[j]);
        atomicAdd(&sSq[f0 + j], q[j]);
    }
    __syncthreads();
    if (tid < 64) {
        atomicAdd(&stats[tid], sSum[tid]);
        atomicAdd(&stats[64 + tid], sSq[tid]);
    }
}

// -------------------- f32x2 node update (K=64), fp16 Ag + Xin, fp16 out ---------
__global__ void __launch_bounds__(128) node_update64(
    const uint4* __restrict__ Agh, const uint4* __restrict__ Xh,
    const float* __restrict__ Wrel, const float* __restrict__ Wroot,
    const float* __restrict__ bias, __half* __restrict__ Outh, float* stats) {
    constexpr int PAD = 66;
    extern __shared__ float sm[];
    float* sA   = sm;
    float* sX   = sA + 64 * PAD;
    ull*   sWr  = (ull*)(sX + 64 * PAD);
    ull*   sWo  = sWr + 32 * 64;
    float* sSum = (float*)(sWo + 32 * 64);
    float* sSq  = sSum + 64;

    const int tid = threadIdx.x;
    const int base = blockIdx.x * 64;

    for (int idx = tid; idx < 32 * 16; idx += 128) {
        int k2 = idx >> 4, c4 = idx & 15;
        float4 r0 = ((const float4*)Wrel)[(2 * k2) * 16 + c4];
        float4 r1 = ((const float4*)Wrel)[(2 * k2 + 1) * 16 + c4];
        ull* p = &sWr[k2 * 64 + c4 * 4];
        p[0] = pack2(r0.x, r1.x); p[1] = pack2(r0.y, r1.y);
        p[2] = pack2(r0.z, r1.z); p[3] = pack2(r0.w, r1.w);
        r0 = ((const float4*)Wroot)[(2 * k2) * 16 + c4];
        r1 = ((const float4*)Wroot)[(2 * k2 + 1) * 16 + c4];
        p = &sWo[k2 * 64 + c4 * 4];
        p[0] = pack2(r0.x, r1.x); p[1] = pack2(r0.y, r1.y);
        p[2] = pack2(r0.z, r1.z); p[3] = pack2(r0.w, r1.w);
    }
    for (int i = tid; i < 64 * 8; i += 128) {
        int r = i >> 3, c = i & 7;
        int n = base + r;
        uint4 va = make_uint4(0u, 0u, 0u, 0u), vx = va;
        if (n < NN) {
            va = Agh[(size_t)n * 8 + c];
            vx = Xh[(size_t)n * 8 + c];
        }
        __half2* hpa = (__half2*)&va;
        __half2* hpx = (__half2*)&vx;
        float* oa = &sA[r * PAD + c * 8];
        float* ox = &sX[r * PAD + c * 8];
#pragma unroll
        for (int j = 0; j < 4; j++) {
            float2 fa = __half22float2(hpa[j]);
            float2 fx = __half22float2(hpx[j]);
            oa[2 * j] = fa.x; oa[2 * j + 1] = fa.y;
            ox[2 * j] = fx.x; ox[2 * j + 1] = fx.y;
        }
    }
    if (tid < 64) { sSum[tid] = 0.f; sSq[tid] = 0.f; }
    __syncthreads();

    const int f0 = (tid & 7) * 2;
    const int ng = (tid >> 3) * 4;

    ull acc2[4][8];
#pragma unroll
    for (int i = 0; i < 4; i++)
#pragma unroll
        for (int j = 0; j < 8; j++) acc2[i][j] = 0ull;

#pragma unroll 2
    for (int k2 = 0; k2 < 32; ++k2) {
        ull av[4], xv[4];
#pragma unroll
        for (int i = 0; i < 4; i++) {
            av[i] = *(const ull*)&sA[(ng + i) * PAD + 2 * k2];
            xv[i] = *(const ull*)&sX[(ng + i) * PAD + 2 * k2];
        }
#pragma unroll
        for (int c = 0; c < 4; c++) {
            ulonglong2 wr = *(const ulonglong2*)&sWr[k2 * 64 + f0 + 16 * c];
            ulonglong2 wo = *(const ulonglong2*)&sWo[k2 * 64 + f0 + 16 * c];
#pragma unroll
            for (int i = 0; i < 4; i++) {
                fma2(acc2[i][2 * c],     av[i], wr.x);
                fma2(acc2[i][2 * c + 1], av[i], wr.y);
                fma2(acc2[i][2 * c],     xv[i], wo.x);
                fma2(acc2[i][2 * c + 1], xv[i], wo.y);
            }
        }
    }

    float bz[8];
#pragma unroll
    for (int c = 0; c < 4; c++) {
        float2 b2 = *(const float2*)&bias[f0 + 16 * c];
        bz[2 * c] = b2.x; bz[2 * c + 1] = b2.y;
    }

    float s[8], q[8];
#pragma unroll
    for (int j = 0; j < 8; j++) { s[j] = 0.f; q[j] = 0.f; }

#pragma unroll
    for (int i = 0; i < 4; i++) {
        int n = base + ng + i;
        if (n < NN) {
#pragma unroll
            for (int c = 0; c < 4; c++) {
                float2 e0 = unpack2(acc2[i][2 * c]);
                float2 e1 = unpack2(acc2[i][2 * c + 1]);
                float o0 = e0.x + e0.y + bz[2 * c];
                float o1 = e1.x + e1.y + bz[2 * c + 1];
                __half2 hv = __floats2half2_rn(o0, o1);
                *(__half2*)&Outh[(size_t)n * 64 + f0 + 16 * c] = hv;
                s[2 * c] += o0; q[2 * c] += o0 * o0;
                s[2 * c + 1] += o1; q[2 * c + 1] += o1 * o1;
            }
        }
    }
#pragma unroll
    for (int c = 0; c < 4; c++) {
        atomicAdd(&sSum[f0 + 16 * c],     s[2 * c]);
        atomicAdd(&sSum[f0 + 16 * c + 1], s[2 * c + 1]);
        atomicAdd(&sSq[f0 + 16 * c],      q[2 * c]);
        atomicAdd(&sSq[f0 + 16 * c + 1],  q[2 * c + 1]);
    }
    __syncthreads();
    if (tid < 64) {
        atomicAdd(&stats[tid], sSum[tid]);
        atomicAdd(&stats[64 + tid], sSq[tid]);
    }
}

// -------------------- BN finalize + apply + ReLU (fp16 in/out, 1 uint4/thread) --
__global__ void __launch_bounds__(256) bn_act_h(
    const uint4* __restrict__ inh, const float* __restrict__ stats,
    const float* __restrict__ g, const float* __restrict__ be,
    uint4* __restrict__ outh) {
    __shared__ float sc[64], sh[64];
    if (threadIdx.x < 64) {
        int f = threadIdx.x;
        const float inv = 1.f / (float)NN;
        float m = stats[f] * inv;
        float var = stats[64 + f] * inv - m * m;
        float s = g[f] * rsqrtf(var + 1e-5f);
        sc[f] = s;
        sh[f] = fmaf(-m, s, be[f]);
    }
    __syncthreads();
    int i = blockIdx.x * blockDim.x + threadIdx.x;
    if (i >= NN * 8) return;
    int c8 = (i & 7) * 8;
    uint4 v = inh[i];
    __half2* hp = (__half2*)&v;
    float o[8];
#pragma unroll
    for (int j = 0; j < 4; j++) {
        float2 f = __half22float2(hp[j]);
        o[2 * j]     = fmaxf(fmaf(f.x, sc[c8 + 2 * j],     sh[c8 + 2 * j]), 0.f);
        o[2 * j + 1] = fmaxf(fmaf(f.y, sc[c8 + 2 * j + 1], sh[c8 + 2 * j + 1]), 0.f);
    }
    __half2 h0 = __floats2half2_rn(o[0], o[1]);
    __half2 h1 = __floats2half2_rn(o[2], o[3]);
    __half2 h2 = __floats2half2_rn(o[4], o[5]);
    __half2 h3 = __floats2half2_rn(o[6], o[7]);
    uint4 ov;
    ov.x = *(unsigned*)&h0; ov.y = *(unsigned*)&h1;
    ov.z = *(unsigned*)&h2; ov.w = *(unsigned*)&h3;
    outh[i] = ov;
}

// -------------------- layer-2 pooled GEMM + MLP head (fp16 agg) -----------------
__global__ void pool2_head(const uint4* __restrict__ Agh, const uint4* __restrict__ Xh,
                           const float* __restrict__ W2rel, const float* __restrict__ W2root,
                           const float* __restrict__ b2, const int* __restrict__ goff,
                           const float* __restrict__ Wl1, const float* __restrict__ bl1,
                           const float* __restrict__ Wl2, const float* __restrict__ bl2,
                           float* __restrict__ out) {
    __shared__ float sAg[64], sXp[64], sPool[64], sz[64];
    int g = blockIdx.x, t = threadIdx.x;
    int beg = goff[g], end = goff[g + 1];
    const __half* ah = (const __half*)Agh;
    const __half* xh = (const __half*)Xh;
    float sa = 0.f, sx = 0.f;
    for (int n = beg; n < end; ++n) {
        sa += __half2float(ah[(size_t)n * 64 + t]);
        sx += __half2float(xh[(size_t)n * 64 + t]);
    }
    sAg[t] = sa; sXp[t] = sx;
    __syncthreads();
    float cnt = (float)(end - beg);
    float acc = cnt * b2[t];
#pragma unroll 8
    for (int k = 0; k < 64; k++)
        acc += sAg[k] * W2rel[k * 64 + t] + sXp[k] * W2root[k * 64 + t];
    sPool[t] = acc / fmaxf(cnt, 1.f);
    __syncthreads();
    float z = bl1[t];
#pragma unroll 8
    for (int k = 0; k < 64; k++) z = fmaf(sPool[k], Wl1[k * 64 + t], z);
    sz[t] = fmaxf(z, 0.f);
    __syncthreads();
    if (t < 6) {
        float o = bl2[t];
#pragma unroll 8
        for (int k = 0; k < 64; k++) o = fmaf(sz[k], Wl2[k * 6 + t], o);
        out[g * 6 + t] = o;
    }
}

// -------------------- launch --------------------
extern "C" void kernel_launch(void* const* d_in, const int* in_sizes, int n_in,
                              void* d_out, int out_size) {
    const float* x     = (const float*)d_in[0];
    const int*   ei    = (const int*)d_in[1];
    const float* ew    = (const float*)d_in[2];
    const int*   batch = (const int*)d_in[3];
    const float *Wrel0 = (const float*)d_in[4],  *Wroot0 = (const float*)d_in[5],  *b0 = (const float*)d_in[6];
    const float *Wrel1 = (const float*)d_in[7],  *Wroot1 = (const float*)d_in[8],  *b1 = (const float*)d_in[9];
    const float *Wrel2 = (const float*)d_in[10], *Wroot2 = (const float*)d_in[11], *b2 = (const float*)d_in[12];
    const float *g0 = (const float*)d_in[13], *be0 = (const float*)d_in[14];
    const float *g1 = (const float*)d_in[15], *be1 = (const float*)d_in[16];
    const float *Wl1 = (const float*)d_in[17], *bl1 = (const float*)d_in[18];
    const float *Wl2 = (const float*)d_in[19], *bl2 = (const float*)d_in[20];
    float* out = (float*)d_out;

    const int* src = ei;
    const int* dst = ei + EE;

    float *pA4, *pX, *pStats;
    uint4 *pAh, *pB, *pH;
    int *pCnt, *pGoff;
    int2* pEpack;
    cudaGetSymbolAddress((void**)&pAh, g_Ah);
    cudaGetSymbolAddress((void**)&pA4, g_A4);
    cudaGetSymbolAddress((void**)&pB, g_B);
    cudaGetSymbolAddress((void**)&pH, g_H);
    cudaGetSymbolAddress((void**)&pX, g_xpad);
    cudaGetSymbolAddress((void**)&pStats, g_stats);
    cudaGetSymbolAddress((void**)&pCnt, g_cnt);
    cudaGetSymbolAddress((void**)&pGoff, g_goff);
    cudaGetSymbolAddress((void**)&pEpack, g_epack);

    const int smem64 = 64 * 66 * 4 * 2 + 32 * 64 * 8 * 2 + 128 * 4;       // 67072 B
    const int smem9  = (64 * 18 * 2 + 9 * 64 * 2 + 128) * (int)sizeof(float);  // 14336 B
    cudaFuncSetAttribute((const void*)node_update64,
                         cudaFuncAttributeMaxDynamicSharedMemorySize, smem64);

    const int NB = (NN + 63) / 64;

    // ---- slotted CSR build + prep (fused) ----
    cudaMemsetAsync(pCnt, 0, NN * sizeof(int));
    place_prep<<<(EE + 511) / 512, 512>>>(src, dst, ew, pCnt, pEpack, x, pX, batch, pGoff);

    // ---- layer 0 ----
    agg_csr4<<<(NN + 63) / 64, 256>>>(pX, pCnt, pEpack, pA4, pStats);
    node_update9<<<NB, 128, smem9>>>(pA4, pX, Wrel0, Wroot0, b0, pB, pStats);
    bn_act_h<<<(NN * 8 + 255) / 256, 256>>>(pB, pStats, g0, be0, pH);

    // ---- layer 1 ----
    agg_csr_h<<<(NN + 31) / 32, 256>>>(pH, pCnt, pEpack, pAh);
    node_update64<<<NB, 128, smem64>>>(pAh, pH, Wrel1, Wroot1, b1, (__half*)pB, pStats + 128);
    bn_act_h<<<(NN * 8 + 255) / 256, 256>>>(pB, pStats + 128, g1, be1, pH);

    // ---- layer 2 ----
    agg_csr_h<<<(NN + 31) / 32, 256>>>(pH, pCnt, pEpack, pAh);
    pool2_head<<<GG, 64>>>(pAh, pH, Wrel2, Wroot2, b2, pGoff, Wl1, bl1, Wl2, bl2, out);
}